// round 4
// baseline (speedup 1.0000x reference)
#include <cuda_runtime.h>
#include <cuda_bf16.h>
#include <math.h>
#include <stdint.h>

// ---------------------------------------------------------------------------
// Problem constants
// ---------------------------------------------------------------------------
#define BATCH   4
#define HW      4096
#define BN_EPS  1e-5f
#define VPIX    5440                 // total pixels across 4 levels
#define VSTRF   (VPIX*256)           // fp32 v batch stride
#define ABF     512                  // bf16 activation row: [256 hi][256 lo]

__device__ __constant__ int c_voff[4]  = {0, 1048576, 1310720, 1376256}; // fp32 v level offs
__device__ __constant__ int c_vpix[4]  = {0, 4096, 5120, 5376};          // pixel-row offs
__device__ __constant__ int c_mact[4]  = {4096, 1024, 256, 64};
__device__ __constant__ int c_vts[5]   = {0, 32, 40, 42, 43};            // vproj m-tile starts
__device__ __constant__ int c_fts[5]   = {0, 128, 160, 168, 170};        // feat-transpose 32px starts

// ---------------------------------------------------------------------------
// Scratch
// ---------------------------------------------------------------------------
__device__ __nv_bfloat16 g_qT [BATCH * HW * ABF];      // query, channel-last split
__device__ __nv_bfloat16 g_fT [BATCH * VPIX * ABF];    // feats, channel-last split
__device__ __nv_bfloat16 g_att[BATCH * HW * ABF];      // sampler out, split
__device__ __nv_bfloat16 g_Woa[3456 * ABF];            // off/attn weights, A-format for compose
__device__ __nv_bfloat16 g_qwT[256 * ABF];             // q_w transposed, B-format
__device__ __nv_bfloat16 g_vw [4 * 256 * ABF];         // v_w, B-format per level
__device__ __nv_bfloat16 g_ow [256 * ABF];             // out_w, B-format
__device__ __nv_bfloat16 g_Wc [384 * 4608];            // composed conv weights [oc][2*2304]
__device__ float g_v  [BATCH * VSTRF];                 // values fp32, channel-last
__device__ float g_cv [BATCH * HW * 384];              // conv out fp32 [pix][384]
__device__ float g_cb [384];
__device__ float g_bns[256], g_bnb[256];

// ---------------------------------------------------------------------------
// Helpers
// ---------------------------------------------------------------------------
__device__ __forceinline__ uint32_t smem_u32(const void* p) {
    uint32_t a;
    asm("{ .reg .u64 t; cvta.to.shared.u64 t, %1; cvt.u32.u64 %0, t; }"
        : "=r"(a) : "l"(p));
    return a;
}
__device__ __forceinline__ void cp16(uint32_t dst, const void* src, bool v) {
    int sz = v ? 16 : 0;
    asm volatile("cp.async.cg.shared.global [%0], [%1], 16, %2;\n"
                 :: "r"(dst), "l"(src), "r"(sz) : "memory");
}
__device__ __forceinline__ void cp_commit() {
    asm volatile("cp.async.commit_group;\n" ::: "memory");
}
__device__ __forceinline__ void cp_wait(int n) {
    if (n == 0) asm volatile("cp.async.wait_group 0;\n" ::: "memory");
    else        asm volatile("cp.async.wait_group 1;\n" ::: "memory");
}
__device__ __forceinline__ void mma_bf16(float* c, const uint32_t* a, const uint32_t* b) {
    asm volatile(
        "mma.sync.aligned.m16n8k16.row.col.f32.bf16.bf16.f32 "
        "{%0,%1,%2,%3}, {%4,%5,%6,%7}, {%8,%9}, {%0,%1,%2,%3};"
        : "+f"(c[0]), "+f"(c[1]), "+f"(c[2]), "+f"(c[3])
        : "r"(a[0]), "r"(a[1]), "r"(a[2]), "r"(a[3]), "r"(b[0]), "r"(b[1]));
}
__device__ __forceinline__ void split_bf(float x, __nv_bfloat16& h, __nv_bfloat16& l) {
    h = __float2bfloat16(x);
    l = __float2bfloat16(x - __bfloat162float(h));
}

// smem: per matrix per stage: 128 rows x 36 words; row = [16w hi][16w lo][4w pad]
#define RSTR     36
#define STG_W    (128 * RSTR)
#define DSMEM_SZ (4 * STG_W * 4)     // A0,A1,B0,B1 = 73728 B

// ---------------------------------------------------------------------------
// Split-bf16 GEMM: D[128 m][128 n] = sum_k A[m][k]*B[n][k], 3-term bf16 MMA.
// MODE 0: compose  (A=g_Woa rows, K=256, out: split-store into g_Wc remapped)
// MODE 1: conv     (A=im2col of qT, K=2304, out: fp32 cv [pix][384] + bias)
// MODE 2: vproj    (A=fT w/ level tables, K=256, out: fp32 v [row][256])
// MODE 3: outproj  (A=att, K=256, out: +resid, BN, SiLU, channel-first fp32)
// 256 threads = 8 warps (2m x 4n), warp tile 64x32.
// ---------------------------------------------------------------------------
template<int MODE>
__global__ __launch_bounds__(256)
void mm_bf3(const __nv_bfloat16* __restrict__ A, long aBatch,
            const __nv_bfloat16* __restrict__ Bw,
            float* __restrict__ Yf, __nv_bfloat16* __restrict__ Yh,
            const float* __restrict__ bias,
            const float* __restrict__ resid,
            const float* __restrict__ bns, const float* __restrict__ bnb)
{
    constexpr int NK = (MODE == 1) ? 72 : 8;
    constexpr int KB = (MODE == 1) ? 2304 : 256;

    extern __shared__ float sm[];

    const int b    = blockIdx.z;
    const int n0   = blockIdx.y * 128;
    const int tid  = threadIdx.x;
    const int wid  = tid >> 5;
    const int lane = tid & 31;
    const int wm   = wid >> 2;
    const int wn   = wid & 3;
    const int gid  = lane >> 2;
    const int tig  = lane & 3;

    int m0 = blockIdx.x * 128, lvl = 0, M_act = 1 << 30;
    const __nv_bfloat16* Bl = Bw;
    if (MODE == 2) {
        while (blockIdx.x >= c_vts[lvl + 1]) lvl++;
        m0    = (blockIdx.x - c_vts[lvl]) * 128;
        M_act = c_mact[lvl];
        Bl    = Bw + lvl * (256 * ABF);
    }
    if (MODE == 0) M_act = 3456;

    const __nv_bfloat16* Ab = A + (long)b * aBatch;
    const uint32_t smb = smem_u32(sm);

    float acc[4][4][4];
#pragma unroll
    for (int mt = 0; mt < 4; mt++)
#pragma unroll
        for (int nt = 0; nt < 4; nt++)
#pragma unroll
            for (int r = 0; r < 4; r++) acc[mt][nt][r] = 0.f;

    auto load_stage = [&](int s) {
        const int buf = s & 1;
        const int k0g = s * 32;
        const int tap = (MODE == 1) ? (s >> 3) : 0;
        const int ic0 = (MODE == 1) ? ((s & 7) * 32) : k0g;
        const int dy = tap / 3 - 1, dx = tap % 3 - 1;
#pragma unroll
        for (int i = 0; i < 4; i++) {
            int ci    = i * 256 + tid;
            int row   = ci >> 3;
            int sub   = ci & 7;
            int plane = sub >> 2;        // 0 hi, 1 lo
            int kc    = sub & 3;         // 16B chunk (8 bf16)
            uint32_t dstA = smb + (buf * STG_W + row * RSTR + plane * 16 + kc * 4) * 4;
            if (MODE == 1) {
                int p  = m0 + row;
                int py = (p >> 6) + dy, px = (p & 63) + dx;
                bool v = (py >= 0) & (py < 64) & (px >= 0) & (px < 64);
                long e = v ? ((long)((py << 6) + px) * ABF + plane * 256 + ic0 + kc * 8) : 0;
                cp16(dstA, Ab + e, v);
            } else {
                int ar = (MODE == 2) ? (c_vpix[lvl] + m0 + row) : (m0 + row);
                bool v = (m0 + row) < M_act;
                long e = v ? ((long)ar * ABF + plane * 256 + ic0 + kc * 8) : 0;
                cp16(dstA, Ab + e, v);
            }
            uint32_t dstB = smb + ((2 + buf) * STG_W + row * RSTR + plane * 16 + kc * 4) * 4;
            cp16(dstB, Bl + (long)(n0 + row) * (2 * KB) + plane * KB + k0g + kc * 8, true);
        }
    };

    load_stage(0); cp_commit();

    for (int s = 0; s < NK; s++) {
        const int buf = s & 1;
        const bool more = (s + 1) < NK;
        if (more) { load_stage(s + 1); cp_commit(); }
        cp_wait(more ? 1 : 0);
        __syncthreads();

        const uint32_t* sA = (const uint32_t*)(sm + buf * STG_W);
        const uint32_t* sB = (const uint32_t*)(sm + (2 + buf) * STG_W);
#pragma unroll
        for (int kk = 0; kk < 2; kk++) {
            const int kw = kk * 8 + tig;
            uint32_t ah[4][4], al[4][4], bh[4][2], bl[4][2];
#pragma unroll
            for (int mt = 0; mt < 4; mt++) {
                int r = wm * 64 + mt * 16 + gid;
                int base = r * RSTR + kw;
                ah[mt][0] = sA[base];
                ah[mt][1] = sA[base + 8 * RSTR];
                ah[mt][2] = sA[base + 4];
                ah[mt][3] = sA[base + 8 * RSTR + 4];
                al[mt][0] = sA[base + 16];
                al[mt][1] = sA[base + 8 * RSTR + 16];
                al[mt][2] = sA[base + 20];
                al[mt][3] = sA[base + 8 * RSTR + 20];
            }
#pragma unroll
            for (int nt = 0; nt < 4; nt++) {
                int n = wn * 32 + nt * 8 + gid;
                int nb = n * RSTR + kw;
                bh[nt][0] = sB[nb];
                bh[nt][1] = sB[nb + 4];
                bl[nt][0] = sB[nb + 16];
                bl[nt][1] = sB[nb + 20];
            }
#pragma unroll
            for (int mt = 0; mt < 4; mt++)
#pragma unroll
                for (int nt = 0; nt < 4; nt++) {
                    mma_bf16(acc[mt][nt], ah[mt], bh[nt]);
                    mma_bf16(acc[mt][nt], ah[mt], bl[nt]);
                    mma_bf16(acc[mt][nt], al[mt], bh[nt]);
                }
        }
        __syncthreads();
    }

    // ---- epilogues ----
#pragma unroll
    for (int mt = 0; mt < 4; mt++) {
        int r0 = m0 + wm * 64 + mt * 16 + gid;
#pragma unroll
        for (int nt = 0; nt < 4; nt++) {
            int col = n0 + wn * 32 + nt * 8 + tig * 2;
#pragma unroll
            for (int h = 0; h < 2; h++) {
                int r = r0 + h * 8;
                float vx = acc[mt][nt][2 * h];
                float vy = acc[mt][nt][2 * h + 1];
                if (MODE == 0) {
                    int tap = r / 384, o = r - tap * 384;
                    long e = (long)o * 4608 + tap * 256 + col;
                    __nv_bfloat16 hh, ll;
                    split_bf(vx, hh, ll); Yh[e]     = hh; Yh[e + 2304]     = ll;
                    split_bf(vy, hh, ll); Yh[e + 1] = hh; Yh[e + 1 + 2304] = ll;
                } else if (MODE == 1) {
                    float2 o = make_float2(vx + bias[col], vy + bias[col + 1]);
                    *(float2*)&Yf[((long)b * HW + r) * 384 + col] = o;
                } else if (MODE == 2) {
                    if (r < M_act) {
                        long row = c_vpix[lvl] + r;
                        *(float2*)&Yf[(long)b * VSTRF + row * 256 + col] =
                            make_float2(vx, vy);
                    }
                } else {
                    const float* qb = resid + (long)b * 256 * HW;
                    float* yb = Yf + (long)b * 256 * HW;
#pragma unroll
                    for (int j = 0; j < 2; j++) {
                        int oc = col + j;
                        float x  = ((j == 0) ? vx : vy) + qb[(long)oc * HW + r];
                        float xn = x * bns[oc] + bnb[oc];
                        yb[(long)oc * HW + r] = xn / (1.f + expf(-xn));
                    }
                }
            }
        }
    }
}

// ---------------------------------------------------------------------------
// Transposes: channel-first fp32 -> channel-last bf16 split [pix][512]
// ---------------------------------------------------------------------------
__global__ __launch_bounds__(256)
void transposeQ(const float* __restrict__ in, __nv_bfloat16* __restrict__ out)
{
    __shared__ float t[32][33];
    const int b = blockIdx.z;
    const float* I = in + (long)b * 256 * HW;
    __nv_bfloat16* O = out + (long)b * HW * ABF;
    const int p0 = blockIdx.x * 32, c0 = blockIdx.y * 32;
    const int tx = threadIdx.x & 31, ty = threadIdx.x >> 5;
#pragma unroll
    for (int i = 0; i < 32; i += 8)
        t[ty + i][tx] = I[(long)(c0 + ty + i) * HW + p0 + tx];
    __syncthreads();
#pragma unroll
    for (int i = 0; i < 32; i += 8) {
        __nv_bfloat16 h, l;
        split_bf(t[tx][ty + i], h, l);
        long e = (long)(p0 + ty + i) * ABF + c0 + tx;
        O[e] = h; O[e + 256] = l;
    }
}

__global__ __launch_bounds__(256)
void transposeF(const float* __restrict__ f0, const float* __restrict__ f1,
                const float* __restrict__ f2, const float* __restrict__ f3,
                __nv_bfloat16* __restrict__ out)
{
    __shared__ float t[32][33];
    int lvl = 0;
    while ((int)blockIdx.x >= c_fts[lvl + 1]) lvl++;
    const int P  = c_mact[lvl];
    const int p0 = (blockIdx.x - c_fts[lvl]) * 32;
    const int b  = blockIdx.z;
    const float* I = (lvl == 0 ? f0 : lvl == 1 ? f1 : lvl == 2 ? f2 : f3)
                   + (long)b * 256 * P;
    __nv_bfloat16* O = out + (long)b * VPIX * ABF + (long)c_vpix[lvl] * ABF;
    const int c0 = blockIdx.y * 32;
    const int tx = threadIdx.x & 31, ty = threadIdx.x >> 5;
#pragma unroll
    for (int i = 0; i < 32; i += 8)
        t[ty + i][tx] = I[(long)(c0 + ty + i) * P + p0 + tx];
    __syncthreads();
#pragma unroll
    for (int i = 0; i < 32; i += 8) {
        __nv_bfloat16 h, l;
        split_bf(t[tx][ty + i], h, l);
        long e = (long)(p0 + ty + i) * ABF + c0 + tx;
        O[e] = h; O[e + 256] = l;
    }
}

// ---------------------------------------------------------------------------
// All weight prep in one launch.
// ---------------------------------------------------------------------------
#define SEG0 262144              // v_w -> g_vw (B-format)
#define SEG1 (SEG0 + 65536)      // out_w -> g_ow
#define SEG2 (SEG1 + 884736)     // off/attn_w -> g_Woa (A-format)
#define SEG3 (SEG2 + 65536)      // q_w^T -> g_qwT (B-format)
#define SEG4 (SEG3 + 384)        // biases
#define SEG5 (SEG4 + 256)        // bn

__global__ void prep_all(const float* __restrict__ qw, const float* __restrict__ vw,
                         const float* __restrict__ ow,
                         const float* __restrict__ offw, const float* __restrict__ attw,
                         const float* __restrict__ offb, const float* __restrict__ attb,
                         const float* __restrict__ bg, const float* __restrict__ bb,
                         const float* __restrict__ bm, const float* __restrict__ bv,
                         __nv_bfloat16* __restrict__ gvw, __nv_bfloat16* __restrict__ gow,
                         __nv_bfloat16* __restrict__ gWoa, __nv_bfloat16* __restrict__ gqwT,
                         float* __restrict__ cb, float* __restrict__ bns,
                         float* __restrict__ bnb)
{
    long i = (long)blockIdx.x * 256 + threadIdx.x;
    if (i < SEG0) {
        long l = i >> 16, rem = i & 65535;
        long o = rem >> 8, c = rem & 255;
        __nv_bfloat16 h, lo;
        split_bf(vw[i], h, lo);
        long e = l * (256 * ABF) + o * ABF + c;
        gvw[e] = h; gvw[e + 256] = lo;
    } else if (i < SEG1) {
        long j = i - SEG0;
        long o = j >> 8, c = j & 255;
        __nv_bfloat16 h, lo;
        split_bf(ow[j], h, lo);
        gow[o * ABF + c] = h; gow[o * ABF + c + 256] = lo;
    } else if (i < SEG2) {
        long j = i - SEG1;
        long row = j >> 8, m = j & 255;
        long tap = row / 384, o = row - tap * 384;
        float v = (o < 256) ? offw[(o * 256 + m) * 9 + tap]
                            : attw[((o - 256) * 256 + m) * 9 + tap];
        __nv_bfloat16 h, lo;
        split_bf(v, h, lo);
        gWoa[row * ABF + m] = h; gWoa[row * ABF + m + 256] = lo;
    } else if (i < SEG3) {
        long j = i - SEG2;
        long c = j >> 8, m = j & 255;
        __nv_bfloat16 h, lo;
        split_bf(qw[m * 256 + c], h, lo);
        gqwT[c * ABF + m] = h; gqwT[c * ABF + m + 256] = lo;
    } else if (i < SEG4) {
        long j = i - SEG3;
        cb[j] = (j < 256) ? offb[j] : attb[j - 256];
    } else if (i < SEG5) {
        long j = i - SEG4;
        float s = bg[j] * rsqrtf(bv[j] + BN_EPS);
        bns[j] = s;
        bnb[j] = bb[j] - bm[j] * s;
    }
}

// ---------------------------------------------------------------------------
// Deformable sampling. One warp per (b, head, pixel). Split-bf16 output.
// ---------------------------------------------------------------------------
__global__ __launch_bounds__(256)
void sample_kernel(const float* __restrict__ cv, const float* __restrict__ v,
                   __nv_bfloat16* __restrict__ att)
{
    const int warp = threadIdx.x >> 5;
    const int lane = threadIdx.x & 31;
    const int pix  = blockIdx.x * 8 + warp;
    const int h    = blockIdx.y;
    const int b    = blockIdx.z;

    const int ph = pix >> 6;
    const int pw = pix & 63;
    const float refx = -1.f + 2.f * (float)pw / 63.f;
    const float refy = -1.f + 2.f * (float)ph / 63.f;

    const float* cvp = cv + ((long)b * HW + pix) * 384;
    float lg = -INFINITY, ox = 0.f, oy = 0.f;
    if (lane < 16) {
        lg = cvp[256 + h * 16 + lane];
        ox = tanhf(cvp[h * 32 + 2 * lane    ]) * 0.25f;
        oy = tanhf(cvp[h * 32 + 2 * lane + 1]) * 0.25f;
    }
    float mx = lg;
#pragma unroll
    for (int s = 16; s > 0; s >>= 1)
        mx = fmaxf(mx, __shfl_xor_sync(0xFFFFFFFFu, mx, s));
    float e = (lane < 16) ? expf(lg - mx) : 0.f;
    float sum = e;
#pragma unroll
    for (int s = 16; s > 0; s >>= 1)
        sum += __shfl_xor_sync(0xFFFFFFFFu, sum, s);
    float wgt = e / sum;

    const float* vb = v + (long)b * VSTRF + h * 32 + lane;

    float acc = 0.f;
#pragma unroll
    for (int i = 0; i < 16; i++) {
        const int lvl = i >> 2;
        const int sz  = 64 >> lvl;
        float aw = __shfl_sync(0xFFFFFFFFu, wgt, i);
        float gx = refx + __shfl_sync(0xFFFFFFFFu, ox, i);
        float gy = refy + __shfl_sync(0xFFFFFFFFu, oy, i);

        float xf = (gx + 1.f) * 0.5f * (float)(sz - 1);
        float yf = (gy + 1.f) * 0.5f * (float)(sz - 1);
        float x0f = floorf(xf), y0f = floorf(yf);
        int x0 = (int)x0f, y0 = (int)y0f;
        int x1 = x0 + 1,  y1 = y0 + 1;
        float wx1 = xf - x0f, wx0 = 1.f - wx1;
        float wy1 = yf - y0f, wy0 = 1.f - wy1;

        const float* vl = vb + c_voff[lvl];
        if (x0 >= 0 && x0 < sz && y0 >= 0 && y0 < sz)
            acc = fmaf(aw * wx0 * wy0, vl[(y0 * sz + x0) * 256], acc);
        if (x1 >= 0 && x1 < sz && y0 >= 0 && y0 < sz)
            acc = fmaf(aw * wx1 * wy0, vl[(y0 * sz + x1) * 256], acc);
        if (x0 >= 0 && x0 < sz && y1 >= 0 && y1 < sz)
            acc = fmaf(aw * wx0 * wy1, vl[(y1 * sz + x0) * 256], acc);
        if (x1 >= 0 && x1 < sz && y1 >= 0 && y1 < sz)
            acc = fmaf(aw * wx1 * wy1, vl[(y1 * sz + x1) * 256], acc);
    }

    __nv_bfloat16 hh, ll;
    split_bf(acc, hh, ll);
    long ebase = ((long)b * HW + pix) * ABF + h * 32 + lane;
    att[ebase] = hh; att[ebase + 256] = ll;
}

// ---------------------------------------------------------------------------
// Launch
// ---------------------------------------------------------------------------
extern "C" void kernel_launch(void* const* d_in, const int* in_sizes, int n_in,
                              void* d_out, int out_size)
{
    const float* query  = (const float*)d_in[0];
    const float* feat0  = (const float*)d_in[1];
    const float* feat1  = (const float*)d_in[2];
    const float* feat2  = (const float*)d_in[3];
    const float* feat3  = (const float*)d_in[4];
    const float* q_w    = (const float*)d_in[5];
    const float* v_w    = (const float*)d_in[6];
    const float* out_w  = (const float*)d_in[7];
    const float* off_w  = (const float*)d_in[8];
    const float* off_b  = (const float*)d_in[9];
    const float* attn_w = (const float*)d_in[10];
    const float* attn_b = (const float*)d_in[11];
    const float* bn_g   = (const float*)d_in[12];
    const float* bn_b   = (const float*)d_in[13];
    const float* bn_m   = (const float*)d_in[14];
    const float* bn_v   = (const float*)d_in[15];
    float* out = (float*)d_out;

    void* p;
    __nv_bfloat16 *gqT, *gfT, *gatt, *gWoa, *gqwT, *gvw, *gow, *gWc;
    float *gv, *gcv, *gcb, *gbns, *gbnb;
    cudaGetSymbolAddress(&p, g_qT);  gqT  = (__nv_bfloat16*)p;
    cudaGetSymbolAddress(&p, g_fT);  gfT  = (__nv_bfloat16*)p;
    cudaGetSymbolAddress(&p, g_att); gatt = (__nv_bfloat16*)p;
    cudaGetSymbolAddress(&p, g_Woa); gWoa = (__nv_bfloat16*)p;
    cudaGetSymbolAddress(&p, g_qwT); gqwT = (__nv_bfloat16*)p;
    cudaGetSymbolAddress(&p, g_vw);  gvw  = (__nv_bfloat16*)p;
    cudaGetSymbolAddress(&p, g_ow);  gow  = (__nv_bfloat16*)p;
    cudaGetSymbolAddress(&p, g_Wc);  gWc  = (__nv_bfloat16*)p;
    cudaGetSymbolAddress(&p, g_v);   gv   = (float*)p;
    cudaGetSymbolAddress(&p, g_cv);  gcv  = (float*)p;
    cudaGetSymbolAddress(&p, g_cb);  gcb  = (float*)p;
    cudaGetSymbolAddress(&p, g_bns); gbns = (float*)p;
    cudaGetSymbolAddress(&p, g_bnb); gbnb = (float*)p;

    cudaFuncSetAttribute(mm_bf3<0>, cudaFuncAttributeMaxDynamicSharedMemorySize, DSMEM_SZ);
    cudaFuncSetAttribute(mm_bf3<1>, cudaFuncAttributeMaxDynamicSharedMemorySize, DSMEM_SZ);
    cudaFuncSetAttribute(mm_bf3<2>, cudaFuncAttributeMaxDynamicSharedMemorySize, DSMEM_SZ);
    cudaFuncSetAttribute(mm_bf3<3>, cudaFuncAttributeMaxDynamicSharedMemorySize, DSMEM_SZ);

    // prep + transposes (independent)
    prep_all<<<(SEG5 + 255) / 256, 256>>>(q_w, v_w, out_w, off_w, attn_w,
                                          off_b, attn_b, bn_g, bn_b, bn_m, bn_v,
                                          gvw, gow, gWoa, gqwT, gcb, gbns, gbnb);
    transposeQ<<<dim3(128, 8, BATCH), 256>>>(query, gqT);
    transposeF<<<dim3(170, 8, BATCH), 256>>>(feat0, feat1, feat2, feat3, gfT);

    // compose conv weights: Wc[o][tap*256+c] = sum_m W[o,m,tap]*q_w[m,c]
    mm_bf3<0><<<dim3(27, 2, 1), 256, DSMEM_SZ>>>(
        gWoa, 0, gqwT, nullptr, gWc, nullptr, nullptr, nullptr, nullptr);

    // v projections (all levels, one launch)
    mm_bf3<2><<<dim3(43, 2, BATCH), 256, DSMEM_SZ>>>(
        gfT, (long)VPIX * ABF, gvw, gv, nullptr, nullptr, nullptr, nullptr, nullptr);

    // fused 3x3 convs directly on query (q-proj composed into weights)
    mm_bf3<1><<<dim3(32, 3, BATCH), 256, DSMEM_SZ>>>(
        gqT, (long)HW * ABF, gWc, gcv, nullptr, gcb, nullptr, nullptr, nullptr);

    // deformable sampling
    sample_kernel<<<dim3(512, 8, BATCH), 256>>>(gcv, gv, gatt);

    // output projection + residual + BN + SiLU
    mm_bf3<3><<<dim3(32, 2, BATCH), 256, DSMEM_SZ>>>(
        gatt, (long)HW * ABF, gow, out, nullptr, nullptr, query, gbns, gbnb);
}

// round 5
// speedup vs baseline: 1.0287x; 1.0287x over previous
#include <cuda_runtime.h>
#include <cuda_bf16.h>
#include <math.h>
#include <stdint.h>

// ---------------------------------------------------------------------------
// Problem constants
// ---------------------------------------------------------------------------
#define BATCH   4
#define HW      4096
#define BN_EPS  1e-5f
#define VPIX    5440                 // total pixels across 4 levels
#define VSTRF   (VPIX*256)           // fp32 v batch stride
#define ABF     512                  // bf16 activation row: [256 hi][256 lo]

__device__ __constant__ int c_voff[4]  = {0, 1048576, 1310720, 1376256}; // fp32 v level offs
__device__ __constant__ int c_vpix[4]  = {0, 4096, 5120, 5376};          // pixel-row offs
__device__ __constant__ int c_mact[4]  = {4096, 1024, 256, 64};
__device__ __constant__ int c_vts[5]   = {0, 32, 40, 42, 43};            // vproj m-tile starts
__device__ __constant__ int c_fts[5]   = {0, 128, 160, 168, 170};        // feat-transpose 32px starts

// ---------------------------------------------------------------------------
// Scratch
// ---------------------------------------------------------------------------
__device__ __nv_bfloat16 g_qT [BATCH * HW * ABF];      // query, channel-last split
__device__ __nv_bfloat16 g_fT [BATCH * VPIX * ABF];    // feats, channel-last split
__device__ __nv_bfloat16 g_att[BATCH * HW * ABF];      // sampler out, split
__device__ __nv_bfloat16 g_Woa[3456 * ABF];            // off/attn weights, A-format for compose
__device__ __nv_bfloat16 g_qwT[256 * ABF];             // q_w transposed, B-format
__device__ __nv_bfloat16 g_vw [4 * 256 * ABF];         // v_w, B-format per level
__device__ __nv_bfloat16 g_ow [256 * ABF];             // out_w, B-format
__device__ __nv_bfloat16 g_Wc [384 * 4608];            // composed conv weights [oc][2*2304]
__device__ float g_v  [BATCH * VSTRF];                 // values fp32, channel-last
__device__ float g_cv [BATCH * HW * 384];              // conv out fp32 [pix][384]
__device__ float g_cb [384];
__device__ float g_bns[256], g_bnb[256];

// ---------------------------------------------------------------------------
// Helpers
// ---------------------------------------------------------------------------
__device__ __forceinline__ uint32_t smem_u32(const void* p) {
    uint32_t a;
    asm("{ .reg .u64 t; cvta.to.shared.u64 t, %1; cvt.u32.u64 %0, t; }"
        : "=r"(a) : "l"(p));
    return a;
}
__device__ __forceinline__ void cp16(uint32_t dst, const void* src, bool v) {
    int sz = v ? 16 : 0;
    asm volatile("cp.async.cg.shared.global [%0], [%1], 16, %2;\n"
                 :: "r"(dst), "l"(src), "r"(sz) : "memory");
}
__device__ __forceinline__ void cp_commit() {
    asm volatile("cp.async.commit_group;\n" ::: "memory");
}
__device__ __forceinline__ void cp_wait2() {
    asm volatile("cp.async.wait_group 2;\n" ::: "memory");
}
__device__ __forceinline__ void mma_bf16(float* c, const uint32_t* a, const uint32_t* b) {
    asm volatile(
        "mma.sync.aligned.m16n8k16.row.col.f32.bf16.bf16.f32 "
        "{%0,%1,%2,%3}, {%4,%5,%6,%7}, {%8,%9}, {%0,%1,%2,%3};"
        : "+f"(c[0]), "+f"(c[1]), "+f"(c[2]), "+f"(c[3])
        : "r"(a[0]), "r"(a[1]), "r"(a[2]), "r"(a[3]), "r"(b[0]), "r"(b[1]));
}
__device__ __forceinline__ void split_bf(float x, __nv_bfloat16& h, __nv_bfloat16& l) {
    h = __float2bfloat16(x);
    l = __float2bfloat16(x - __bfloat162float(h));
}

// compact swizzled smem: per matrix per stage 128 rows x 32 words (128B rows).
// logical word w in row r lives at physical word ((w>>2)^(r&7))*4 + (w&3).
#define STG_W    4096                 // words per matrix-stage (16 KB)
#define DSMEM_SZ (6 * STG_W * 4)      // A0..A2, B0..B2 = 96 KB

__device__ __forceinline__ const uint32_t& LW(const uint32_t* p, int r, int w) {
    return p[r * 32 + (((w >> 2) ^ (r & 7)) << 2) + (w & 3)];
}

// ---------------------------------------------------------------------------
// Split-bf16 GEMM: D[128 m][128 n] = sum_k A[m][k]*B[n][k], 3-term bf16 MMA.
// MODE 0: compose  (A=g_Woa rows, K=256, out: split-store into g_Wc remapped)
// MODE 1: conv     (A=im2col of qT, K=2304, out: fp32 cv [pix][384] + bias)
// MODE 2: vproj    (A=fT w/ level tables, K=256, out: fp32 v [row][256])
// MODE 3: outproj  (A=att, K=256, out: +resid, BN, SiLU, channel-first fp32)
// 256 threads = 8 warps (2m x 4n), warp tile 64x32. 3-stage cp.async ring.
// ---------------------------------------------------------------------------
template<int MODE>
__global__ __launch_bounds__(256, 2)
void mm_bf3(const __nv_bfloat16* __restrict__ A, long aBatch,
            const __nv_bfloat16* __restrict__ Bw,
            float* __restrict__ Yf, __nv_bfloat16* __restrict__ Yh,
            const float* __restrict__ bias,
            const float* __restrict__ resid,
            const float* __restrict__ bns, const float* __restrict__ bnb)
{
    constexpr int NK = (MODE == 1) ? 72 : 8;
    constexpr int KB = (MODE == 1) ? 2304 : 256;

    extern __shared__ float sm[];

    const int b    = blockIdx.z;
    const int n0   = blockIdx.y * 128;
    const int tid  = threadIdx.x;
    const int wid  = tid >> 5;
    const int lane = tid & 31;
    const int wm   = wid >> 2;
    const int wn   = wid & 3;
    const int gid  = lane >> 2;
    const int tig  = lane & 3;

    int m0 = blockIdx.x * 128, lvl = 0, M_act = 1 << 30;
    const __nv_bfloat16* Bl = Bw;
    if (MODE == 2) {
        while (blockIdx.x >= c_vts[lvl + 1]) lvl++;
        m0    = (blockIdx.x - c_vts[lvl]) * 128;
        M_act = c_mact[lvl];
        Bl    = Bw + lvl * (256 * ABF);
    }
    if (MODE == 0) M_act = 3456;

    const __nv_bfloat16* Ab = A + (long)b * aBatch;
    const uint32_t smb = smem_u32(sm);

    float acc[4][4][4];
#pragma unroll
    for (int mt = 0; mt < 4; mt++)
#pragma unroll
        for (int nt = 0; nt < 4; nt++)
#pragma unroll
            for (int r = 0; r < 4; r++) acc[mt][nt][r] = 0.f;

    auto load_stage = [&](int s) {
        const int buf = s % 3;
        const int k0g = s * 32;
        const int tap = (MODE == 1) ? (s >> 3) : 0;
        const int ic0 = (MODE == 1) ? ((s & 7) * 32) : k0g;
        const int dy = tap / 3 - 1, dx = tap % 3 - 1;
#pragma unroll
        for (int i = 0; i < 4; i++) {
            int ci    = i * 256 + tid;
            int row   = ci >> 3;
            int sub   = ci & 7;          // logical 16B chunk 0..7
            int plane = sub >> 2;        // 0 hi, 1 lo
            int kc    = sub & 3;
            int phys  = sub ^ (row & 7);
            uint32_t dstA = smb + buf * 16384 + row * 128 + phys * 16;
            if (MODE == 1) {
                int p  = m0 + row;
                int py = (p >> 6) + dy, px = (p & 63) + dx;
                bool v = (py >= 0) & (py < 64) & (px >= 0) & (px < 64);
                long e = v ? ((long)((py << 6) + px) * ABF + plane * 256 + ic0 + kc * 8) : 0;
                cp16(dstA, Ab + e, v);
            } else {
                int ar = (MODE == 2) ? (c_vpix[lvl] + m0 + row) : (m0 + row);
                bool v = (m0 + row) < M_act;
                long e = v ? ((long)ar * ABF + plane * 256 + ic0 + kc * 8) : 0;
                cp16(dstA, Ab + e, v);
            }
            uint32_t dstB = smb + (3 + buf) * 16384 + row * 128 + phys * 16;
            cp16(dstB, Bl + (long)(n0 + row) * (2 * KB) + plane * KB + k0g + kc * 8, true);
        }
    };

    // prologue: 3 stages in flight
    load_stage(0); cp_commit();
    if (NK > 1) load_stage(1); cp_commit();
    if (NK > 2) load_stage(2); cp_commit();

    for (int s = 0; s < NK; s++) {
        const int buf = s % 3;
        cp_wait2();
        __syncthreads();

        const uint32_t* sA = (const uint32_t*)sm + buf * STG_W;
        const uint32_t* sB = (const uint32_t*)sm + (3 + buf) * STG_W;
#pragma unroll
        for (int kk = 0; kk < 2; kk++) {
            const int kw = kk * 8 + tig;
            uint32_t ah[4][4], al[4][4], bh[4][2], bl[4][2];
#pragma unroll
            for (int mt = 0; mt < 4; mt++) {
                int r = wm * 64 + mt * 16 + gid;
                ah[mt][0] = LW(sA, r,     kw);
                ah[mt][1] = LW(sA, r + 8, kw);
                ah[mt][2] = LW(sA, r,     kw + 4);
                ah[mt][3] = LW(sA, r + 8, kw + 4);
                al[mt][0] = LW(sA, r,     kw + 16);
                al[mt][1] = LW(sA, r + 8, kw + 16);
                al[mt][2] = LW(sA, r,     kw + 20);
                al[mt][3] = LW(sA, r + 8, kw + 20);
            }
#pragma unroll
            for (int nt = 0; nt < 4; nt++) {
                int n = wn * 32 + nt * 8 + gid;
                bh[nt][0] = LW(sB, n, kw);
                bh[nt][1] = LW(sB, n, kw + 4);
                bl[nt][0] = LW(sB, n, kw + 16);
                bl[nt][1] = LW(sB, n, kw + 20);
            }
#pragma unroll
            for (int mt = 0; mt < 4; mt++)
#pragma unroll
                for (int nt = 0; nt < 4; nt++) {
                    mma_bf16(acc[mt][nt], ah[mt], bh[nt]);
                    mma_bf16(acc[mt][nt], ah[mt], bl[nt]);
                    mma_bf16(acc[mt][nt], al[mt], bh[nt]);
                }
        }
        __syncthreads();
        if (s + 3 < NK) load_stage(s + 3);
        cp_commit();
    }

    // ---- epilogues ----
#pragma unroll
    for (int mt = 0; mt < 4; mt++) {
        int r0 = m0 + wm * 64 + mt * 16 + gid;
#pragma unroll
        for (int nt = 0; nt < 4; nt++) {
            int col = n0 + wn * 32 + nt * 8 + tig * 2;
#pragma unroll
            for (int h = 0; h < 2; h++) {
                int r = r0 + h * 8;
                float vx = acc[mt][nt][2 * h];
                float vy = acc[mt][nt][2 * h + 1];
                if (MODE == 0) {
                    int tap = r / 384, o = r - tap * 384;
                    long e = (long)o * 4608 + tap * 256 + col;
                    __nv_bfloat16 hh, ll;
                    split_bf(vx, hh, ll); Yh[e]     = hh; Yh[e + 2304]     = ll;
                    split_bf(vy, hh, ll); Yh[e + 1] = hh; Yh[e + 1 + 2304] = ll;
                } else if (MODE == 1) {
                    float2 o = make_float2(vx + bias[col], vy + bias[col + 1]);
                    *(float2*)&Yf[((long)b * HW + r) * 384 + col] = o;
                } else if (MODE == 2) {
                    if (r < M_act) {
                        long row = c_vpix[lvl] + r;
                        *(float2*)&Yf[(long)b * VSTRF + row * 256 + col] =
                            make_float2(vx, vy);
                    }
                } else {
                    const float* qb = resid + (long)b * 256 * HW;
                    float* yb = Yf + (long)b * 256 * HW;
#pragma unroll
                    for (int j = 0; j < 2; j++) {
                        int oc = col + j;
                        float x  = ((j == 0) ? vx : vy) + qb[(long)oc * HW + r];
                        float xn = x * bns[oc] + bnb[oc];
                        yb[(long)oc * HW + r] = xn / (1.f + expf(-xn));
                    }
                }
            }
        }
    }
}

// ---------------------------------------------------------------------------
// Transposes: channel-first fp32 -> channel-last bf16 split [pix][512]
// ---------------------------------------------------------------------------
__global__ __launch_bounds__(256)
void transposeQ(const float* __restrict__ in, __nv_bfloat16* __restrict__ out)
{
    __shared__ float t[32][33];
    const int b = blockIdx.z;
    const float* I = in + (long)b * 256 * HW;
    __nv_bfloat16* O = out + (long)b * HW * ABF;
    const int p0 = blockIdx.x * 32, c0 = blockIdx.y * 32;
    const int tx = threadIdx.x & 31, ty = threadIdx.x >> 5;
#pragma unroll
    for (int i = 0; i < 32; i += 8)
        t[ty + i][tx] = I[(long)(c0 + ty + i) * HW + p0 + tx];
    __syncthreads();
#pragma unroll
    for (int i = 0; i < 32; i += 8) {
        __nv_bfloat16 h, l;
        split_bf(t[tx][ty + i], h, l);
        long e = (long)(p0 + ty + i) * ABF + c0 + tx;
        O[e] = h; O[e + 256] = l;
    }
}

__global__ __launch_bounds__(256)
void transposeF(const float* __restrict__ f0, const float* __restrict__ f1,
                const float* __restrict__ f2, const float* __restrict__ f3,
                __nv_bfloat16* __restrict__ out)
{
    __shared__ float t[32][33];
    int lvl = 0;
    while ((int)blockIdx.x >= c_fts[lvl + 1]) lvl++;
    const int P  = c_mact[lvl];
    const int p0 = (blockIdx.x - c_fts[lvl]) * 32;
    const int b  = blockIdx.z;
    const float* I = (lvl == 0 ? f0 : lvl == 1 ? f1 : lvl == 2 ? f2 : f3)
                   + (long)b * 256 * P;
    __nv_bfloat16* O = out + (long)b * VPIX * ABF + (long)c_vpix[lvl] * ABF;
    const int c0 = blockIdx.y * 32;
    const int tx = threadIdx.x & 31, ty = threadIdx.x >> 5;
#pragma unroll
    for (int i = 0; i < 32; i += 8)
        t[ty + i][tx] = I[(long)(c0 + ty + i) * P + p0 + tx];
    __syncthreads();
#pragma unroll
    for (int i = 0; i < 32; i += 8) {
        __nv_bfloat16 h, l;
        split_bf(t[tx][ty + i], h, l);
        long e = (long)(p0 + ty + i) * ABF + c0 + tx;
        O[e] = h; O[e + 256] = l;
    }
}

// ---------------------------------------------------------------------------
// All weight prep in one launch.
// ---------------------------------------------------------------------------
#define SEG0 262144              // v_w -> g_vw (B-format)
#define SEG1 (SEG0 + 65536)      // out_w -> g_ow
#define SEG2 (SEG1 + 884736)     // off/attn_w -> g_Woa (A-format)
#define SEG3 (SEG2 + 65536)      // q_w^T -> g_qwT (B-format)
#define SEG4 (SEG3 + 384)        // biases
#define SEG5 (SEG4 + 256)        // bn

__global__ void prep_all(const float* __restrict__ qw, const float* __restrict__ vw,
                         const float* __restrict__ ow,
                         const float* __restrict__ offw, const float* __restrict__ attw,
                         const float* __restrict__ offb, const float* __restrict__ attb,
                         const float* __restrict__ bg, const float* __restrict__ bb,
                         const float* __restrict__ bm, const float* __restrict__ bv,
                         __nv_bfloat16* __restrict__ gvw, __nv_bfloat16* __restrict__ gow,
                         __nv_bfloat16* __restrict__ gWoa, __nv_bfloat16* __restrict__ gqwT,
                         float* __restrict__ cb, float* __restrict__ bns,
                         float* __restrict__ bnb)
{
    long i = (long)blockIdx.x * 256 + threadIdx.x;
    if (i < SEG0) {
        long l = i >> 16, rem = i & 65535;
        long o = rem >> 8, c = rem & 255;
        __nv_bfloat16 h, lo;
        split_bf(vw[i], h, lo);
        long e = l * (256 * ABF) + o * ABF + c;
        gvw[e] = h; gvw[e + 256] = lo;
    } else if (i < SEG1) {
        long j = i - SEG0;
        long o = j >> 8, c = j & 255;
        __nv_bfloat16 h, lo;
        split_bf(ow[j], h, lo);
        gow[o * ABF + c] = h; gow[o * ABF + c + 256] = lo;
    } else if (i < SEG2) {
        long j = i - SEG1;
        long row = j >> 8, m = j & 255;
        long tap = row / 384, o = row - tap * 384;
        float v = (o < 256) ? offw[(o * 256 + m) * 9 + tap]
                            : attw[((o - 256) * 256 + m) * 9 + tap];
        __nv_bfloat16 h, lo;
        split_bf(v, h, lo);
        gWoa[row * ABF + m] = h; gWoa[row * ABF + m + 256] = lo;
    } else if (i < SEG3) {
        long j = i - SEG2;
        long c = j >> 8, m = j & 255;
        __nv_bfloat16 h, lo;
        split_bf(qw[m * 256 + c], h, lo);
        gqwT[c * ABF + m] = h; gqwT[c * ABF + m + 256] = lo;
    } else if (i < SEG4) {
        long j = i - SEG3;
        cb[j] = (j < 256) ? offb[j] : attb[j - 256];
    } else if (i < SEG5) {
        long j = i - SEG4;
        float s = bg[j] * rsqrtf(bv[j] + BN_EPS);
        bns[j] = s;
        bnb[j] = bb[j] - bm[j] * s;
    }
}

// ---------------------------------------------------------------------------
// Deformable sampling. One warp per (b, head, pixel). Split-bf16 output.
// ---------------------------------------------------------------------------
__global__ __launch_bounds__(256)
void sample_kernel(const float* __restrict__ cv, const float* __restrict__ v,
                   __nv_bfloat16* __restrict__ att)
{
    const int warp = threadIdx.x >> 5;
    const int lane = threadIdx.x & 31;
    const int pix  = blockIdx.x * 8 + warp;
    const int h    = blockIdx.y;
    const int b    = blockIdx.z;

    const int ph = pix >> 6;
    const int pw = pix & 63;
    const float refx = -1.f + 2.f * (float)pw / 63.f;
    const float refy = -1.f + 2.f * (float)ph / 63.f;

    const float* cvp = cv + ((long)b * HW + pix) * 384;
    float lg = -INFINITY, ox = 0.f, oy = 0.f;
    if (lane < 16) {
        lg = cvp[256 + h * 16 + lane];
        ox = tanhf(cvp[h * 32 + 2 * lane    ]) * 0.25f;
        oy = tanhf(cvp[h * 32 + 2 * lane + 1]) * 0.25f;
    }
    float mx = lg;
#pragma unroll
    for (int s = 16; s > 0; s >>= 1)
        mx = fmaxf(mx, __shfl_xor_sync(0xFFFFFFFFu, mx, s));
    float e = (lane < 16) ? expf(lg - mx) : 0.f;
    float sum = e;
#pragma unroll
    for (int s = 16; s > 0; s >>= 1)
        sum += __shfl_xor_sync(0xFFFFFFFFu, sum, s);
    float wgt = e / sum;

    const float* vb = v + (long)b * VSTRF + h * 32 + lane;

    float acc = 0.f;
#pragma unroll
    for (int i = 0; i < 16; i++) {
        const int lvl = i >> 2;
        const int sz  = 64 >> lvl;
        float aw = __shfl_sync(0xFFFFFFFFu, wgt, i);
        float gx = refx + __shfl_sync(0xFFFFFFFFu, ox, i);
        float gy = refy + __shfl_sync(0xFFFFFFFFu, oy, i);

        float xf = (gx + 1.f) * 0.5f * (float)(sz - 1);
        float yf = (gy + 1.f) * 0.5f * (float)(sz - 1);
        float x0f = floorf(xf), y0f = floorf(yf);
        int x0 = (int)x0f, y0 = (int)y0f;
        int x1 = x0 + 1,  y1 = y0 + 1;
        float wx1 = xf - x0f, wx0 = 1.f - wx1;
        float wy1 = yf - y0f, wy0 = 1.f - wy1;

        const float* vl = vb + c_voff[lvl];
        if (x0 >= 0 && x0 < sz && y0 >= 0 && y0 < sz)
            acc = fmaf(aw * wx0 * wy0, vl[(y0 * sz + x0) * 256], acc);
        if (x1 >= 0 && x1 < sz && y0 >= 0 && y0 < sz)
            acc = fmaf(aw * wx1 * wy0, vl[(y0 * sz + x1) * 256], acc);
        if (x0 >= 0 && x0 < sz && y1 >= 0 && y1 < sz)
            acc = fmaf(aw * wx0 * wy1, vl[(y1 * sz + x0) * 256], acc);
        if (x1 >= 0 && x1 < sz && y1 >= 0 && y1 < sz)
            acc = fmaf(aw * wx1 * wy1, vl[(y1 * sz + x1) * 256], acc);
    }

    __nv_bfloat16 hh, ll;
    split_bf(acc, hh, ll);
    long ebase = ((long)b * HW + pix) * ABF + h * 32 + lane;
    att[ebase] = hh; att[ebase + 256] = ll;
}

// ---------------------------------------------------------------------------
// Launch
// ---------------------------------------------------------------------------
extern "C" void kernel_launch(void* const* d_in, const int* in_sizes, int n_in,
                              void* d_out, int out_size)
{
    const float* query  = (const float*)d_in[0];
    const float* feat0  = (const float*)d_in[1];
    const float* feat1  = (const float*)d_in[2];
    const float* feat2  = (const float*)d_in[3];
    const float* feat3  = (const float*)d_in[4];
    const float* q_w    = (const float*)d_in[5];
    const float* v_w    = (const float*)d_in[6];
    const float* out_w  = (const float*)d_in[7];
    const float* off_w  = (const float*)d_in[8];
    const float* off_b  = (const float*)d_in[9];
    const float* attn_w = (const float*)d_in[10];
    const float* attn_b = (const float*)d_in[11];
    const float* bn_g   = (const float*)d_in[12];
    const float* bn_b   = (const float*)d_in[13];
    const float* bn_m   = (const float*)d_in[14];
    const float* bn_v   = (const float*)d_in[15];
    float* out = (float*)d_out;

    void* p;
    __nv_bfloat16 *gqT, *gfT, *gatt, *gWoa, *gqwT, *gvw, *gow, *gWc;
    float *gv, *gcv, *gcb, *gbns, *gbnb;
    cudaGetSymbolAddress(&p, g_qT);  gqT  = (__nv_bfloat16*)p;
    cudaGetSymbolAddress(&p, g_fT);  gfT  = (__nv_bfloat16*)p;
    cudaGetSymbolAddress(&p, g_att); gatt = (__nv_bfloat16*)p;
    cudaGetSymbolAddress(&p, g_Woa); gWoa = (__nv_bfloat16*)p;
    cudaGetSymbolAddress(&p, g_qwT); gqwT = (__nv_bfloat16*)p;
    cudaGetSymbolAddress(&p, g_vw);  gvw  = (__nv_bfloat16*)p;
    cudaGetSymbolAddress(&p, g_ow);  gow  = (__nv_bfloat16*)p;
    cudaGetSymbolAddress(&p, g_Wc);  gWc  = (__nv_bfloat16*)p;
    cudaGetSymbolAddress(&p, g_v);   gv   = (float*)p;
    cudaGetSymbolAddress(&p, g_cv);  gcv  = (float*)p;
    cudaGetSymbolAddress(&p, g_cb);  gcb  = (float*)p;
    cudaGetSymbolAddress(&p, g_bns); gbns = (float*)p;
    cudaGetSymbolAddress(&p, g_bnb); gbnb = (float*)p;

    cudaFuncSetAttribute(mm_bf3<0>, cudaFuncAttributeMaxDynamicSharedMemorySize, DSMEM_SZ);
    cudaFuncSetAttribute(mm_bf3<1>, cudaFuncAttributeMaxDynamicSharedMemorySize, DSMEM_SZ);
    cudaFuncSetAttribute(mm_bf3<2>, cudaFuncAttributeMaxDynamicSharedMemorySize, DSMEM_SZ);
    cudaFuncSetAttribute(mm_bf3<3>, cudaFuncAttributeMaxDynamicSharedMemorySize, DSMEM_SZ);

    // prep + transposes (independent)
    prep_all<<<(SEG5 + 255) / 256, 256>>>(q_w, v_w, out_w, off_w, attn_w,
                                          off_b, attn_b, bn_g, bn_b, bn_m, bn_v,
                                          gvw, gow, gWoa, gqwT, gcb, gbns, gbnb);
    transposeQ<<<dim3(128, 8, BATCH), 256>>>(query, gqT);
    transposeF<<<dim3(170, 8, BATCH), 256>>>(feat0, feat1, feat2, feat3, gfT);

    // compose conv weights: Wc[o][tap*256+c] = sum_m W[o,m,tap]*q_w[m,c]
    mm_bf3<0><<<dim3(27, 2, 1), 256, DSMEM_SZ>>>(
        gWoa, 0, gqwT, nullptr, gWc, nullptr, nullptr, nullptr, nullptr);

    // v projections (all levels, one launch)
    mm_bf3<2><<<dim3(43, 2, BATCH), 256, DSMEM_SZ>>>(
        gfT, (long)VPIX * ABF, gvw, gv, nullptr, nullptr, nullptr, nullptr, nullptr);

    // fused 3x3 convs directly on query (q-proj composed into weights)
    mm_bf3<1><<<dim3(32, 3, BATCH), 256, DSMEM_SZ>>>(
        gqT, (long)HW * ABF, gWc, gcv, nullptr, gcb, nullptr, nullptr, nullptr);

    // deformable sampling
    sample_kernel<<<dim3(512, 8, BATCH), 256>>>(gcv, gv, gatt);

    // output projection + residual + BN + SiLU
    mm_bf3<3><<<dim3(32, 2, BATCH), 256, DSMEM_SZ>>>(
        gatt, (long)HW * ABF, gow, out, nullptr, nullptr, query, gbns, gbnb);
}

// round 6
// speedup vs baseline: 1.0319x; 1.0031x over previous
#include <cuda_runtime.h>
#include <cuda_bf16.h>
#include <math.h>
#include <stdint.h>

// ---------------------------------------------------------------------------
// Problem constants
// ---------------------------------------------------------------------------
#define BATCH   4
#define HW      4096
#define BN_EPS  1e-5f
#define VPIX    5440                 // total pixels across 4 levels
#define VSTRF   (VPIX*256)           // fp32 v batch stride
#define ABF     512                  // bf16 activation row: [256 hi][256 lo]

__device__ __constant__ int c_voff[4]  = {0, 1048576, 1310720, 1376256}; // fp32 v level offs
__device__ __constant__ int c_vpix[4]  = {0, 4096, 5120, 5376};          // pixel-row offs
__device__ __constant__ int c_mact[4]  = {4096, 1024, 256, 64};
__device__ __constant__ int c_vts[5]   = {0, 32, 40, 42, 43};            // vproj m-tile starts
__device__ __constant__ int c_fts[5]   = {0, 128, 160, 168, 170};        // feat-transpose 32px starts

// ---------------------------------------------------------------------------
// Scratch
// ---------------------------------------------------------------------------
__device__ __nv_bfloat16 g_qT [BATCH * HW * ABF];      // query, channel-last split
__device__ __nv_bfloat16 g_fT [BATCH * VPIX * ABF];    // feats, channel-last split
__device__ __nv_bfloat16 g_att[BATCH * HW * ABF];      // sampler out, split
__device__ __nv_bfloat16 g_Woa[3456 * ABF];            // off/attn weights, A-format for compose
__device__ __nv_bfloat16 g_qwT[256 * ABF];             // q_w transposed, B-format
__device__ __nv_bfloat16 g_vw [4 * 256 * ABF];         // v_w, B-format per level
__device__ __nv_bfloat16 g_ow [256 * ABF];             // out_w, B-format
__device__ __nv_bfloat16 g_Wc [384 * 4608];            // composed conv weights [oc][2*2304]
__device__ float g_v  [BATCH * VSTRF];                 // values fp32, channel-last
__device__ float g_cv [BATCH * HW * 384];              // conv out fp32 [pix][384]
__device__ float g_cb [384];
__device__ float g_bns[256], g_bnb[256];

// ---------------------------------------------------------------------------
// Helpers
// ---------------------------------------------------------------------------
__device__ __forceinline__ uint32_t smem_u32(const void* p) {
    uint32_t a;
    asm("{ .reg .u64 t; cvta.to.shared.u64 t, %1; cvt.u32.u64 %0, t; }"
        : "=r"(a) : "l"(p));
    return a;
}
__device__ __forceinline__ void cp16(uint32_t dst, const void* src, bool v) {
    int sz = v ? 16 : 0;
    asm volatile("cp.async.cg.shared.global [%0], [%1], 16, %2;\n"
                 :: "r"(dst), "l"(src), "r"(sz) : "memory");
}
__device__ __forceinline__ void cp_commit() {
    asm volatile("cp.async.commit_group;\n" ::: "memory");
}
__device__ __forceinline__ void cp_wait2() {
    asm volatile("cp.async.wait_group 2;\n" ::: "memory");
}
__device__ __forceinline__ void mma_bf16(float* c, const uint32_t* a, const uint32_t* b) {
    asm volatile(
        "mma.sync.aligned.m16n8k16.row.col.f32.bf16.bf16.f32 "
        "{%0,%1,%2,%3}, {%4,%5,%6,%7}, {%8,%9}, {%0,%1,%2,%3};"
        : "+f"(c[0]), "+f"(c[1]), "+f"(c[2]), "+f"(c[3])
        : "r"(a[0]), "r"(a[1]), "r"(a[2]), "r"(a[3]), "r"(b[0]), "r"(b[1]));
}
#define LDSM_X4(r0, r1, r2, r3, addr) \
    asm volatile("ldmatrix.sync.aligned.m8n8.x4.shared.b16 {%0,%1,%2,%3}, [%4];" \
        : "=r"(r0), "=r"(r1), "=r"(r2), "=r"(r3) : "r"(addr))

__device__ __forceinline__ void split_bf(float x, __nv_bfloat16& h, __nv_bfloat16& l) {
    h = __float2bfloat16(x);
    l = __float2bfloat16(x - __bfloat162float(h));
}

// compact swizzled smem: per matrix per stage 128 rows x 32 words (128B rows).
// logical 16B-chunk c in row r lives at physical chunk c ^ (r & 7).
#define STG_W    4096                 // words per matrix-stage (16 KB)
#define DSMEM_SZ (6 * STG_W * 4)      // A0..A2, B0..B2 = 96 KB

// ---------------------------------------------------------------------------
// Split-bf16 GEMM: D[128 m][128 n] = sum_k A[m][k]*B[n][k], 3-term bf16 MMA.
// MODE 0: compose  (A=g_Woa rows, K=256, out: split-store into g_Wc remapped)
// MODE 1: conv     (A=im2col of qT, K=2304, out: fp32 cv [pix][384] + bias)
// MODE 2: vproj    (A=fT w/ level tables, K=256, out: fp32 v [row][256])
// MODE 3: outproj  (A=att, K=256, out: +resid, BN, SiLU, channel-first fp32)
// 256 threads = 8 warps (2m x 4n), warp tile 64x32. 3-stage cp.async ring.
// Fragments loaded via ldmatrix.x4 (12 per kk instead of 48 LDS.32).
// ---------------------------------------------------------------------------
template<int MODE>
__global__ __launch_bounds__(256, 2)
void mm_bf3(const __nv_bfloat16* __restrict__ A, long aBatch,
            const __nv_bfloat16* __restrict__ Bw,
            float* __restrict__ Yf, __nv_bfloat16* __restrict__ Yh,
            const float* __restrict__ bias,
            const float* __restrict__ resid,
            const float* __restrict__ bns, const float* __restrict__ bnb)
{
    constexpr int NK = (MODE == 1) ? 72 : 8;
    constexpr int KB = (MODE == 1) ? 2304 : 256;

    extern __shared__ float sm[];

    const int b    = blockIdx.z;
    const int n0   = blockIdx.y * 128;
    const int tid  = threadIdx.x;
    const int wid  = tid >> 5;
    const int lane = tid & 31;
    const int wm   = wid >> 2;
    const int wn   = wid & 3;
    const int gid  = lane >> 2;
    const int tig  = lane & 3;
    // ldmatrix lane decomposition
    const int l8 = lane & 7;
    const int lm = (lane >> 3) & 1;
    const int lh = lane >> 4;

    int m0 = blockIdx.x * 128, lvl = 0, M_act = 1 << 30;
    const __nv_bfloat16* Bl = Bw;
    if (MODE == 2) {
        while (blockIdx.x >= c_vts[lvl + 1]) lvl++;
        m0    = (blockIdx.x - c_vts[lvl]) * 128;
        M_act = c_mact[lvl];
        Bl    = Bw + lvl * (256 * ABF);
    }
    if (MODE == 0) M_act = 3456;

    const __nv_bfloat16* Ab = A + (long)b * aBatch;
    const uint32_t smb = smem_u32(sm);

    float acc[4][4][4];
#pragma unroll
    for (int mt = 0; mt < 4; mt++)
#pragma unroll
        for (int nt = 0; nt < 4; nt++)
#pragma unroll
            for (int r = 0; r < 4; r++) acc[mt][nt][r] = 0.f;

    auto load_stage = [&](int s) {
        const int buf = s % 3;
        const int k0g = s * 32;
        const int tap = (MODE == 1) ? (s >> 3) : 0;
        const int ic0 = (MODE == 1) ? ((s & 7) * 32) : k0g;
        const int dy = tap / 3 - 1, dx = tap % 3 - 1;
#pragma unroll
        for (int i = 0; i < 4; i++) {
            int ci    = i * 256 + tid;
            int row   = ci >> 3;
            int sub   = ci & 7;          // logical 16B chunk 0..7
            int plane = sub >> 2;        // 0 hi, 1 lo
            int kc    = sub & 3;
            int phys  = sub ^ (row & 7);
            uint32_t dstA = smb + buf * 16384 + row * 128 + phys * 16;
            if (MODE == 1) {
                int p  = m0 + row;
                int py = (p >> 6) + dy, px = (p & 63) + dx;
                bool v = (py >= 0) & (py < 64) & (px >= 0) & (px < 64);
                long e = v ? ((long)((py << 6) + px) * ABF + plane * 256 + ic0 + kc * 8) : 0;
                cp16(dstA, Ab + e, v);
            } else {
                int ar = (MODE == 2) ? (c_vpix[lvl] + m0 + row) : (m0 + row);
                bool v = (m0 + row) < M_act;
                long e = v ? ((long)ar * ABF + plane * 256 + ic0 + kc * 8) : 0;
                cp16(dstA, Ab + e, v);
            }
            uint32_t dstB = smb + (3 + buf) * 16384 + row * 128 + phys * 16;
            cp16(dstB, Bl + (long)(n0 + row) * (2 * KB) + plane * KB + k0g + kc * 8, true);
        }
    };

    // prologue: 3 stages in flight
    load_stage(0); cp_commit();
    if (NK > 1) load_stage(1); cp_commit();
    if (NK > 2) load_stage(2); cp_commit();

    for (int s = 0; s < NK; s++) {
        const int buf = s % 3;
        cp_wait2();
        __syncthreads();

        const uint32_t aBase = smb + buf * 16384;
        const uint32_t bBase = smb + (3 + buf) * 16384;
#pragma unroll
        for (int kk = 0; kk < 2; kk++) {
            const int chH = kk * 2 + lh;       // hi chunk for this lane
            const int chL = chH + 4;           // lo chunk
            uint32_t ah[4][4], al[4][4], bh[4][2], bl[4][2];
#pragma unroll
            for (int mt = 0; mt < 4; mt++) {
                int row = wm * 64 + mt * 16 + l8 + lm * 8;
                uint32_t base = aBase + row * 128;
                uint32_t aH = base + ((chH ^ l8) << 4);
                uint32_t aL = base + ((chL ^ l8) << 4);
                LDSM_X4(ah[mt][0], ah[mt][1], ah[mt][2], ah[mt][3], aH);
                LDSM_X4(al[mt][0], al[mt][1], al[mt][2], al[mt][3], aL);
            }
#pragma unroll
            for (int np = 0; np < 2; np++) {
                int row = wn * 32 + np * 16 + l8 + lm * 8;
                uint32_t base = bBase + row * 128;
                uint32_t bH = base + ((chH ^ l8) << 4);
                uint32_t bL = base + ((chL ^ l8) << 4);
                LDSM_X4(bh[2 * np][0], bh[2 * np + 1][0],
                        bh[2 * np][1], bh[2 * np + 1][1], bH);
                LDSM_X4(bl[2 * np][0], bl[2 * np + 1][0],
                        bl[2 * np][1], bl[2 * np + 1][1], bL);
            }
#pragma unroll
            for (int mt = 0; mt < 4; mt++)
#pragma unroll
                for (int nt = 0; nt < 4; nt++) {
                    mma_bf16(acc[mt][nt], ah[mt], bh[nt]);
                    mma_bf16(acc[mt][nt], ah[mt], bl[nt]);
                    mma_bf16(acc[mt][nt], al[mt], bh[nt]);
                }
        }
        __syncthreads();
        if (s + 3 < NK) load_stage(s + 3);
        cp_commit();
    }

    // ---- epilogues ----
#pragma unroll
    for (int mt = 0; mt < 4; mt++) {
        int r0 = m0 + wm * 64 + mt * 16 + gid;
#pragma unroll
        for (int nt = 0; nt < 4; nt++) {
            int col = n0 + wn * 32 + nt * 8 + tig * 2;
#pragma unroll
            for (int h = 0; h < 2; h++) {
                int r = r0 + h * 8;
                float vx = acc[mt][nt][2 * h];
                float vy = acc[mt][nt][2 * h + 1];
                if (MODE == 0) {
                    int tap = r / 384, o = r - tap * 384;
                    long e = (long)o * 4608 + tap * 256 + col;
                    __nv_bfloat16 hh, ll;
                    split_bf(vx, hh, ll); Yh[e]     = hh; Yh[e + 2304]     = ll;
                    split_bf(vy, hh, ll); Yh[e + 1] = hh; Yh[e + 1 + 2304] = ll;
                } else if (MODE == 1) {
                    float2 o = make_float2(vx + bias[col], vy + bias[col + 1]);
                    *(float2*)&Yf[((long)b * HW + r) * 384 + col] = o;
                } else if (MODE == 2) {
                    if (r < M_act) {
                        long row = c_vpix[lvl] + r;
                        *(float2*)&Yf[(long)b * VSTRF + row * 256 + col] =
                            make_float2(vx, vy);
                    }
                } else {
                    const float* qb = resid + (long)b * 256 * HW;
                    float* yb = Yf + (long)b * 256 * HW;
#pragma unroll
                    for (int j = 0; j < 2; j++) {
                        int oc = col + j;
                        float x  = ((j == 0) ? vx : vy) + qb[(long)oc * HW + r];
                        float xn = x * bns[oc] + bnb[oc];
                        yb[(long)oc * HW + r] = xn / (1.f + expf(-xn));
                    }
                }
            }
        }
    }
}

// ---------------------------------------------------------------------------
// Transposes: channel-first fp32 -> channel-last bf16 split [pix][512]
// ---------------------------------------------------------------------------
__global__ __launch_bounds__(256)
void transposeQ(const float* __restrict__ in, __nv_bfloat16* __restrict__ out)
{
    __shared__ float t[32][33];
    const int b = blockIdx.z;
    const float* I = in + (long)b * 256 * HW;
    __nv_bfloat16* O = out + (long)b * HW * ABF;
    const int p0 = blockIdx.x * 32, c0 = blockIdx.y * 32;
    const int tx = threadIdx.x & 31, ty = threadIdx.x >> 5;
#pragma unroll
    for (int i = 0; i < 32; i += 8)
        t[ty + i][tx] = I[(long)(c0 + ty + i) * HW + p0 + tx];
    __syncthreads();
#pragma unroll
    for (int i = 0; i < 32; i += 8) {
        __nv_bfloat16 h, l;
        split_bf(t[tx][ty + i], h, l);
        long e = (long)(p0 + ty + i) * ABF + c0 + tx;
        O[e] = h; O[e + 256] = l;
    }
}

__global__ __launch_bounds__(256)
void transposeF(const float* __restrict__ f0, const float* __restrict__ f1,
                const float* __restrict__ f2, const float* __restrict__ f3,
                __nv_bfloat16* __restrict__ out)
{
    __shared__ float t[32][33];
    int lvl = 0;
    while ((int)blockIdx.x >= c_fts[lvl + 1]) lvl++;
    const int P  = c_mact[lvl];
    const int p0 = (blockIdx.x - c_fts[lvl]) * 32;
    const int b  = blockIdx.z;
    const float* I = (lvl == 0 ? f0 : lvl == 1 ? f1 : lvl == 2 ? f2 : f3)
                   + (long)b * 256 * P;
    __nv_bfloat16* O = out + (long)b * VPIX * ABF + (long)c_vpix[lvl] * ABF;
    const int c0 = blockIdx.y * 32;
    const int tx = threadIdx.x & 31, ty = threadIdx.x >> 5;
#pragma unroll
    for (int i = 0; i < 32; i += 8)
        t[ty + i][tx] = I[(long)(c0 + ty + i) * P + p0 + tx];
    __syncthreads();
#pragma unroll
    for (int i = 0; i < 32; i += 8) {
        __nv_bfloat16 h, l;
        split_bf(t[tx][ty + i], h, l);
        long e = (long)(p0 + ty + i) * ABF + c0 + tx;
        O[e] = h; O[e + 256] = l;
    }
}

// ---------------------------------------------------------------------------
// All weight prep in one launch.
// ---------------------------------------------------------------------------
#define SEG0 262144              // v_w -> g_vw (B-format)
#define SEG1 (SEG0 + 65536)      // out_w -> g_ow
#define SEG2 (SEG1 + 884736)     // off/attn_w -> g_Woa (A-format)
#define SEG3 (SEG2 + 65536)      // q_w^T -> g_qwT (B-format)
#define SEG4 (SEG3 + 384)        // biases
#define SEG5 (SEG4 + 256)        // bn

__global__ void prep_all(const float* __restrict__ qw, const float* __restrict__ vw,
                         const float* __restrict__ ow,
                         const float* __restrict__ offw, const float* __restrict__ attw,
                         const float* __restrict__ offb, const float* __restrict__ attb,
                         const float* __restrict__ bg, const float* __restrict__ bb,
                         const float* __restrict__ bm, const float* __restrict__ bv,
                         __nv_bfloat16* __restrict__ gvw, __nv_bfloat16* __restrict__ gow,
                         __nv_bfloat16* __restrict__ gWoa, __nv_bfloat16* __restrict__ gqwT,
                         float* __restrict__ cb, float* __restrict__ bns,
                         float* __restrict__ bnb)
{
    long i = (long)blockIdx.x * 256 + threadIdx.x;
    if (i < SEG0) {
        long l = i >> 16, rem = i & 65535;
        long o = rem >> 8, c = rem & 255;
        __nv_bfloat16 h, lo;
        split_bf(vw[i], h, lo);
        long e = l * (256 * ABF) + o * ABF + c;
        gvw[e] = h; gvw[e + 256] = lo;
    } else if (i < SEG1) {
        long j = i - SEG0;
        long o = j >> 8, c = j & 255;
        __nv_bfloat16 h, lo;
        split_bf(ow[j], h, lo);
        gow[o * ABF + c] = h; gow[o * ABF + c + 256] = lo;
    } else if (i < SEG2) {
        long j = i - SEG1;
        long row = j >> 8, m = j & 255;
        long tap = row / 384, o = row - tap * 384;
        float v = (o < 256) ? offw[(o * 256 + m) * 9 + tap]
                            : attw[((o - 256) * 256 + m) * 9 + tap];
        __nv_bfloat16 h, lo;
        split_bf(v, h, lo);
        gWoa[row * ABF + m] = h; gWoa[row * ABF + m + 256] = lo;
    } else if (i < SEG3) {
        long j = i - SEG2;
        long c = j >> 8, m = j & 255;
        __nv_bfloat16 h, lo;
        split_bf(qw[m * 256 + c], h, lo);
        gqwT[c * ABF + m] = h; gqwT[c * ABF + m + 256] = lo;
    } else if (i < SEG4) {
        long j = i - SEG3;
        cb[j] = (j < 256) ? offb[j] : attb[j - 256];
    } else if (i < SEG5) {
        long j = i - SEG4;
        float s = bg[j] * rsqrtf(bv[j] + BN_EPS);
        bns[j] = s;
        bnb[j] = bb[j] - bm[j] * s;
    }
}

// ---------------------------------------------------------------------------
// Deformable sampling. One warp per (b, head, pixel). Split-bf16 output.
// ---------------------------------------------------------------------------
__global__ __launch_bounds__(256)
void sample_kernel(const float* __restrict__ cv, const float* __restrict__ v,
                   __nv_bfloat16* __restrict__ att)
{
    const int warp = threadIdx.x >> 5;
    const int lane = threadIdx.x & 31;
    const int pix  = blockIdx.x * 8 + warp;
    const int h    = blockIdx.y;
    const int b    = blockIdx.z;

    const int ph = pix >> 6;
    const int pw = pix & 63;
    const float refx = -1.f + 2.f * (float)pw / 63.f;
    const float refy = -1.f + 2.f * (float)ph / 63.f;

    const float* cvp = cv + ((long)b * HW + pix) * 384;
    float lg = -INFINITY, ox = 0.f, oy = 0.f;
    if (lane < 16) {
        lg = cvp[256 + h * 16 + lane];
        ox = tanhf(cvp[h * 32 + 2 * lane    ]) * 0.25f;
        oy = tanhf(cvp[h * 32 + 2 * lane + 1]) * 0.25f;
    }
    float mx = lg;
#pragma unroll
    for (int s = 16; s > 0; s >>= 1)
        mx = fmaxf(mx, __shfl_xor_sync(0xFFFFFFFFu, mx, s));
    float e = (lane < 16) ? expf(lg - mx) : 0.f;
    float sum = e;
#pragma unroll
    for (int s = 16; s > 0; s >>= 1)
        sum += __shfl_xor_sync(0xFFFFFFFFu, sum, s);
    float wgt = e / sum;

    const float* vb = v + (long)b * VSTRF + h * 32 + lane;

    float acc = 0.f;
#pragma unroll
    for (int i = 0; i < 16; i++) {
        const int lvl = i >> 2;
        const int sz  = 64 >> lvl;
        float aw = __shfl_sync(0xFFFFFFFFu, wgt, i);
        float gx = refx + __shfl_sync(0xFFFFFFFFu, ox, i);
        float gy = refy + __shfl_sync(0xFFFFFFFFu, oy, i);

        float xf = (gx + 1.f) * 0.5f * (float)(sz - 1);
        float yf = (gy + 1.f) * 0.5f * (float)(sz - 1);
        float x0f = floorf(xf), y0f = floorf(yf);
        int x0 = (int)x0f, y0 = (int)y0f;
        int x1 = x0 + 1,  y1 = y0 + 1;
        float wx1 = xf - x0f, wx0 = 1.f - wx1;
        float wy1 = yf - y0f, wy0 = 1.f - wy1;

        const float* vl = vb + c_voff[lvl];
        if (x0 >= 0 && x0 < sz && y0 >= 0 && y0 < sz)
            acc = fmaf(aw * wx0 * wy0, vl[(y0 * sz + x0) * 256], acc);
        if (x1 >= 0 && x1 < sz && y0 >= 0 && y0 < sz)
            acc = fmaf(aw * wx1 * wy0, vl[(y0 * sz + x1) * 256], acc);
        if (x0 >= 0 && x0 < sz && y1 >= 0 && y1 < sz)
            acc = fmaf(aw * wx0 * wy1, vl[(y1 * sz + x0) * 256], acc);
        if (x1 >= 0 && x1 < sz && y1 >= 0 && y1 < sz)
            acc = fmaf(aw * wx1 * wy1, vl[(y1 * sz + x1) * 256], acc);
    }

    __nv_bfloat16 hh, ll;
    split_bf(acc, hh, ll);
    long ebase = ((long)b * HW + pix) * ABF + h * 32 + lane;
    att[ebase] = hh; att[ebase + 256] = ll;
}

// ---------------------------------------------------------------------------
// Launch. Ordered so the conv GEMM is the 4th launch (ncu capture slot).
// ---------------------------------------------------------------------------
extern "C" void kernel_launch(void* const* d_in, const int* in_sizes, int n_in,
                              void* d_out, int out_size)
{
    const float* query  = (const float*)d_in[0];
    const float* feat0  = (const float*)d_in[1];
    const float* feat1  = (const float*)d_in[2];
    const float* feat2  = (const float*)d_in[3];
    const float* feat3  = (const float*)d_in[4];
    const float* q_w    = (const float*)d_in[5];
    const float* v_w    = (const float*)d_in[6];
    const float* out_w  = (const float*)d_in[7];
    const float* off_w  = (const float*)d_in[8];
    const float* off_b  = (const float*)d_in[9];
    const float* attn_w = (const float*)d_in[10];
    const float* attn_b = (const float*)d_in[11];
    const float* bn_g   = (const float*)d_in[12];
    const float* bn_b   = (const float*)d_in[13];
    const float* bn_m   = (const float*)d_in[14];
    const float* bn_v   = (const float*)d_in[15];
    float* out = (float*)d_out;

    void* p;
    __nv_bfloat16 *gqT, *gfT, *gatt, *gWoa, *gqwT, *gvw, *gow, *gWc;
    float *gv, *gcv, *gcb, *gbns, *gbnb;
    cudaGetSymbolAddress(&p, g_qT);  gqT  = (__nv_bfloat16*)p;
    cudaGetSymbolAddress(&p, g_fT);  gfT  = (__nv_bfloat16*)p;
    cudaGetSymbolAddress(&p, g_att); gatt = (__nv_bfloat16*)p;
    cudaGetSymbolAddress(&p, g_Woa); gWoa = (__nv_bfloat16*)p;
    cudaGetSymbolAddress(&p, g_qwT); gqwT = (__nv_bfloat16*)p;
    cudaGetSymbolAddress(&p, g_vw);  gvw  = (__nv_bfloat16*)p;
    cudaGetSymbolAddress(&p, g_ow);  gow  = (__nv_bfloat16*)p;
    cudaGetSymbolAddress(&p, g_Wc);  gWc  = (__nv_bfloat16*)p;
    cudaGetSymbolAddress(&p, g_v);   gv   = (float*)p;
    cudaGetSymbolAddress(&p, g_cv);  gcv  = (float*)p;
    cudaGetSymbolAddress(&p, g_cb);  gcb  = (float*)p;
    cudaGetSymbolAddress(&p, g_bns); gbns = (float*)p;
    cudaGetSymbolAddress(&p, g_bnb); gbnb = (float*)p;

    cudaFuncSetAttribute(mm_bf3<0>, cudaFuncAttributeMaxDynamicSharedMemorySize, DSMEM_SZ);
    cudaFuncSetAttribute(mm_bf3<1>, cudaFuncAttributeMaxDynamicSharedMemorySize, DSMEM_SZ);
    cudaFuncSetAttribute(mm_bf3<2>, cudaFuncAttributeMaxDynamicSharedMemorySize, DSMEM_SZ);
    cudaFuncSetAttribute(mm_bf3<3>, cudaFuncAttributeMaxDynamicSharedMemorySize, DSMEM_SZ);

    // 1. weight prep
    prep_all<<<(SEG5 + 255) / 256, 256>>>(q_w, v_w, out_w, off_w, attn_w,
                                          off_b, attn_b, bn_g, bn_b, bn_m, bn_v,
                                          gvw, gow, gWoa, gqwT, gcb, gbns, gbnb);
    // 2. query transpose
    transposeQ<<<dim3(128, 8, BATCH), 256>>>(query, gqT);

    // 3. compose conv weights: Wc[o][tap*256+c] = sum_m W[o,m,tap]*q_w[m,c]
    mm_bf3<0><<<dim3(27, 2, 1), 256, DSMEM_SZ>>>(
        gWoa, 0, gqwT, nullptr, gWc, nullptr, nullptr, nullptr, nullptr);

    // 4. fused 3x3 convs directly on query  <-- ncu capture slot
    mm_bf3<1><<<dim3(32, 3, BATCH), 256, DSMEM_SZ>>>(
        gqT, (long)HW * ABF, gWc, gcv, nullptr, gcb, nullptr, nullptr, nullptr);

    // 5. feat transposes
    transposeF<<<dim3(170, 8, BATCH), 256>>>(feat0, feat1, feat2, feat3, gfT);

    // 6. v projections (all levels, one launch)
    mm_bf3<2><<<dim3(43, 2, BATCH), 256, DSMEM_SZ>>>(
        gfT, (long)VPIX * ABF, gvw, gv, nullptr, nullptr, nullptr, nullptr, nullptr);

    // 7. deformable sampling
    sample_kernel<<<dim3(512, 8, BATCH), 256>>>(gcv, gv, gatt);

    // 8. output projection + residual + BN + SiLU
    mm_bf3<3><<<dim3(32, 2, BATCH), 256, DSMEM_SZ>>>(
        gatt, (long)HW * ABF, gow, out, nullptr, nullptr, query, gbns, gbnb);
}

// round 7
// speedup vs baseline: 1.0501x; 1.0177x over previous
#include <cuda_runtime.h>
#include <cuda_bf16.h>
#include <math.h>
#include <stdint.h>

// ---------------------------------------------------------------------------
// Problem constants
// ---------------------------------------------------------------------------
#define BATCH   4
#define HW      4096
#define BN_EPS  1e-5f
#define VPIX    5440                 // total pixels across 4 levels
#define VSTRF   (VPIX*256)           // fp32 v batch stride
#define ABF     512                  // bf16 activation row: [256 hi][256 lo]

__device__ __constant__ int c_voff[4]  = {0, 1048576, 1310720, 1376256}; // fp32 v level offs
__device__ __constant__ int c_vpix[4]  = {0, 4096, 5120, 5376};          // pixel-row offs
__device__ __constant__ int c_mact[4]  = {4096, 1024, 256, 64};
__device__ __constant__ int c_vts[5]   = {0, 32, 40, 42, 43};            // vproj m-tile starts
__device__ __constant__ int c_fts[6]   = {0, 128, 256, 288, 296, 298};   // transpose tile starts (q,f0..f3)
__device__ __constant__ int c_tapd[9]  = {-33280, -32768, -32256, -512, 0, 512,
                                           32256, 32768, 33280};         // (dy*64+dx)*ABF

// ---------------------------------------------------------------------------
// Scratch
// ---------------------------------------------------------------------------
__device__ __nv_bfloat16 g_qT [BATCH * HW * ABF];      // query, channel-last split
__device__ __nv_bfloat16 g_fT [BATCH * VPIX * ABF];    // feats, channel-last split
__device__ __nv_bfloat16 g_att[BATCH * HW * ABF];      // sampler out, split
__device__ __nv_bfloat16 g_Woa[3456 * ABF];            // off/attn weights, A-format for compose
__device__ __nv_bfloat16 g_qwT[256 * ABF];             // q_w transposed, B-format
__device__ __nv_bfloat16 g_vw [4 * 256 * ABF];         // v_w, B-format per level
__device__ __nv_bfloat16 g_ow [256 * ABF];             // out_w, B-format
__device__ __nv_bfloat16 g_Wc [384 * 4608];            // composed conv weights [oc][2*2304]
__device__ float g_v  [BATCH * VSTRF];                 // values fp32, channel-last
__device__ float g_cv [BATCH * HW * 384];              // conv out fp32 [pix][384]
__device__ float g_cb [384];
__device__ float g_bns[256], g_bnb[256];

// ---------------------------------------------------------------------------
// Helpers
// ---------------------------------------------------------------------------
__device__ __forceinline__ uint32_t smem_u32(const void* p) {
    uint32_t a;
    asm("{ .reg .u64 t; cvta.to.shared.u64 t, %1; cvt.u32.u64 %0, t; }"
        : "=r"(a) : "l"(p));
    return a;
}
__device__ __forceinline__ void cp16(uint32_t dst, const void* src, bool v) {
    int sz = v ? 16 : 0;
    asm volatile("cp.async.cg.shared.global [%0], [%1], 16, %2;\n"
                 :: "r"(dst), "l"(src), "r"(sz) : "memory");
}
__device__ __forceinline__ void cp_commit() {
    asm volatile("cp.async.commit_group;\n" ::: "memory");
}
__device__ __forceinline__ void cp_wait2() {
    asm volatile("cp.async.wait_group 2;\n" ::: "memory");
}
__device__ __forceinline__ void mma_bf16(float* c, const uint32_t* a, const uint32_t* b) {
    asm volatile(
        "mma.sync.aligned.m16n8k16.row.col.f32.bf16.bf16.f32 "
        "{%0,%1,%2,%3}, {%4,%5,%6,%7}, {%8,%9}, {%0,%1,%2,%3};"
        : "+f"(c[0]), "+f"(c[1]), "+f"(c[2]), "+f"(c[3])
        : "r"(a[0]), "r"(a[1]), "r"(a[2]), "r"(a[3]), "r"(b[0]), "r"(b[1]));
}
#define LDSM_X4(r0, r1, r2, r3, addr) \
    asm volatile("ldmatrix.sync.aligned.m8n8.x4.shared.b16 {%0,%1,%2,%3}, [%4];" \
        : "=r"(r0), "=r"(r1), "=r"(r2), "=r"(r3) : "r"(addr))

__device__ __forceinline__ void split_bf(float x, __nv_bfloat16& h, __nv_bfloat16& l) {
    h = __float2bfloat16(x);
    l = __float2bfloat16(x - __bfloat162float(h));
}

// compact swizzled smem: per matrix per stage 128 rows x 128B; 16B-chunk c of
// row r lives at physical chunk c ^ (r & 7).
#define STG_B    16384
#define DSMEM_SZ (6 * STG_B)          // A0..A2, B0..B2 = 96 KB

// ---------------------------------------------------------------------------
// Unified split-bf16 GEMM. lmode: 0=compose, 1=merged conv+vproj, 3=outproj.
// Per-CTA mode: 0 compose / 1 conv / 2 vproj / 3 outproj.
// D[128m][128n] = sum_k A[m][k]*B[n][k] via 3-term bf16 m16n8k16.
// 256 threads = 8 warps (2m x 4n), warp tile 64x32, 3-stage cp.async ring.
// All load addresses are hoisted: per-thread 1 A-base, 1 B-ptr, packed
// validity masks; per-stage address math is ~5 integer ops.
// ---------------------------------------------------------------------------
__global__ __launch_bounds__(256, 2)
void mm_all(int lmode, const float* __restrict__ resid, float* __restrict__ outp)
{
    extern __shared__ float sm[];

    const int b    = blockIdx.z;
    const int tid  = threadIdx.x;
    const int wid  = tid >> 5;
    const int lane = tid & 31;
    const int wm   = wid >> 2;
    const int wn   = wid & 3;
    const int gid  = lane >> 2;
    const int tig  = lane & 3;
    const int l8   = lane & 7;
    const int lm   = (lane >> 3) & 1;
    const int lh   = lane >> 4;

    // ---- per-CTA mode & geometry ----
    int mode, m0, n0, NK, KB, lvl = 0, M_act = 1 << 30;
    const __nv_bfloat16 *Abase, *Bbase;
    if (lmode == 1) {
        int t = blockIdx.x;
        if (t < 96) {
            mode = 1; m0 = (t & 31) * 128; n0 = (t >> 5) * 128;
            NK = 72; KB = 2304;
            Abase = g_qT + (long)b * HW * ABF;
            Bbase = g_Wc;
        } else {
            mode = 2; int tv = t - 96;
            int nt = (tv >= 43) ? 1 : 0;
            int mtile = tv - nt * 43;
            while (mtile >= c_vts[lvl + 1]) lvl++;
            m0 = (mtile - c_vts[lvl]) * 128;
            n0 = nt * 128;
            M_act = c_mact[lvl];
            NK = 8; KB = 256;
            Abase = g_fT + (long)b * VPIX * ABF + (long)c_vpix[lvl] * ABF;
            Bbase = g_vw + lvl * 256 * ABF;
        }
    } else if (lmode == 0) {
        mode = 0; m0 = blockIdx.x * 128; n0 = blockIdx.y * 128;
        NK = 8; KB = 256;
        Abase = g_Woa; Bbase = g_qwT;
    } else {
        mode = 3; m0 = blockIdx.x * 128; n0 = blockIdx.y * 128;
        NK = 8; KB = 256;
        Abase = g_att + (long)b * HW * ABF; Bbase = g_ow;
    }
    const bool isConv = (mode == 1);

    // ---- hoisted per-thread loader state ----
    const int r0   = tid >> 3;       // base row 0..31 (rows r0+32i)
    const int sub  = tid & 7;
    const int plane = sub >> 2;
    const int kc   = sub & 3;
    const int phys = sub ^ (r0 & 7);
    const uint32_t smb = smem_u32(sm);

    const __nv_bfloat16* aB = Abase + (long)(m0 + r0) * ABF + plane * 256 + kc * 8;
    const __nv_bfloat16* bP = Bbase + (long)(n0 + r0) * (2 * KB) + plane * KB + kc * 8;
    const int aRowStep = 32 * ABF;               // per-i A advance
    const int bRowStep = 32 * (2 * KB);          // per-i B advance
    const uint32_t dA0 = smb + r0 * 128 + phys * 16;
    const uint32_t dB0 = dA0 + 3 * STG_B;

    // validity masks: 9 bits per row-i, packed 2 rows per u32
    uint32_t mAlo = 0, mAhi = 0;
#pragma unroll
    for (int i = 0; i < 4; i++) {
        uint32_t m9;
        if (isConv) {
            int pix = m0 + r0 + 32 * i;
            int py0 = pix >> 6, px0 = pix & 63;
            m9 = 0;
#pragma unroll
            for (int tp = 0; tp < 9; tp++) {
                int py = py0 + tp / 3 - 1, px = px0 + tp % 3 - 1;
                if (py >= 0 && py < 64 && px >= 0 && px < 64) m9 |= 1u << tp;
            }
        } else {
            m9 = ((m0 + r0 + 32 * i) < M_act) ? 0x1FFu : 0u;
        }
        if (i < 2) mAlo |= m9 << (9 * i);
        else       mAhi |= m9 << (9 * (i - 2));
    }

    float acc[4][4][4];
#pragma unroll
    for (int mt = 0; mt < 4; mt++)
#pragma unroll
        for (int nt = 0; nt < 4; nt++)
#pragma unroll
            for (int r = 0; r < 4; r++) acc[mt][nt][r] = 0.f;

    auto load_stage = [&](int s, int buf) {
        const int tap  = s >> 3;
        const int aoff = (isConv ? c_tapd[tap] : 0) + ((s & 7) << 5);
        const __nv_bfloat16* ap = aB + aoff;
        const __nv_bfloat16* bp = bP + s * 32;
        const uint32_t dA = dA0 + buf * STG_B;
        const uint32_t dB = dB0 + buf * STG_B;
#pragma unroll
        for (int i = 0; i < 4; i++) {
            uint32_t mm = (i < 2 ? mAlo : mAhi) >> (tap + 9 * (i & 1));
            bool v = mm & 1;
            cp16(dA + i * 4096, v ? (ap + i * aRowStep) : (const void*)Abase, v);
            cp16(dB + i * 4096, bp + i * bRowStep, true);
        }
    };

    // prologue: 3 stages in flight
    load_stage(0, 0); cp_commit();
    if (NK > 1) load_stage(1, 1); cp_commit();
    if (NK > 2) load_stage(2, 2); cp_commit();

    int buf = 0;
    for (int s = 0; s < NK; s++) {
        cp_wait2();
        __syncthreads();

        const uint32_t aBase_s = smb + buf * STG_B;
        const uint32_t bBase_s = smb + (3 + buf) * STG_B;
#pragma unroll
        for (int kk = 0; kk < 2; kk++) {
            const int chH = kk * 2 + lh;
            const int chL = chH + 4;
            uint32_t ah[4][4], al[4][4], bh[4][2], bl[4][2];
#pragma unroll
            for (int mt = 0; mt < 4; mt++) {
                int row = wm * 64 + mt * 16 + l8 + lm * 8;
                uint32_t base = aBase_s + row * 128;
                LDSM_X4(ah[mt][0], ah[mt][1], ah[mt][2], ah[mt][3],
                        base + ((chH ^ l8) << 4));
                LDSM_X4(al[mt][0], al[mt][1], al[mt][2], al[mt][3],
                        base + ((chL ^ l8) << 4));
            }
#pragma unroll
            for (int np = 0; np < 2; np++) {
                int row = wn * 32 + np * 16 + l8 + lm * 8;
                uint32_t base = bBase_s + row * 128;
                LDSM_X4(bh[2 * np][0], bh[2 * np + 1][0],
                        bh[2 * np][1], bh[2 * np + 1][1],
                        base + ((chH ^ l8) << 4));
                LDSM_X4(bl[2 * np][0], bl[2 * np + 1][0],
                        bl[2 * np][1], bl[2 * np + 1][1],
                        base + ((chL ^ l8) << 4));
            }
#pragma unroll
            for (int mt = 0; mt < 4; mt++)
#pragma unroll
                for (int nt = 0; nt < 4; nt++) {
                    mma_bf16(acc[mt][nt], ah[mt], bh[nt]);
                    mma_bf16(acc[mt][nt], ah[mt], bl[nt]);
                    mma_bf16(acc[mt][nt], al[mt], bh[nt]);
                }
        }
        __syncthreads();
        if (s + 3 < NK) load_stage(s + 3, buf);
        cp_commit();
        buf = (buf == 2) ? 0 : buf + 1;
    }

    // ---- epilogues ----
#pragma unroll
    for (int mt = 0; mt < 4; mt++) {
        int r0e = m0 + wm * 64 + mt * 16 + gid;
#pragma unroll
        for (int nt = 0; nt < 4; nt++) {
            int col = n0 + wn * 32 + nt * 8 + tig * 2;
#pragma unroll
            for (int h = 0; h < 2; h++) {
                int r = r0e + h * 8;
                float vx = acc[mt][nt][2 * h];
                float vy = acc[mt][nt][2 * h + 1];
                if (mode == 0) {
                    int tap = r / 384, o = r - tap * 384;
                    long e = (long)o * 4608 + tap * 256 + col;
                    __nv_bfloat16 hh, ll;
                    split_bf(vx, hh, ll); g_Wc[e]     = hh; g_Wc[e + 2304]     = ll;
                    split_bf(vy, hh, ll); g_Wc[e + 1] = hh; g_Wc[e + 1 + 2304] = ll;
                } else if (mode == 1) {
                    float2 o = make_float2(vx + g_cb[col], vy + g_cb[col + 1]);
                    *(float2*)&g_cv[((long)b * HW + r) * 384 + col] = o;
                } else if (mode == 2) {
                    if (r < M_act) {
                        long row = c_vpix[lvl] + r;
                        *(float2*)&g_v[(long)b * VSTRF + row * 256 + col] =
                            make_float2(vx, vy);
                    }
                } else {
                    const float* qb = resid + (long)b * 256 * HW;
                    float* yb = outp + (long)b * 256 * HW;
#pragma unroll
                    for (int j = 0; j < 2; j++) {
                        int oc = col + j;
                        float x  = ((j == 0) ? vx : vy) + qb[(long)oc * HW + r];
                        float xn = x * g_bns[oc] + g_bnb[oc];
                        yb[(long)oc * HW + r] = xn / (1.f + expf(-xn));
                    }
                }
            }
        }
    }
}

// ---------------------------------------------------------------------------
// One transpose kernel for query + all 4 feature levels.
// channel-first fp32 -> channel-last bf16 split [pix][512]
// ---------------------------------------------------------------------------
__global__ __launch_bounds__(256)
void transposeAll(const float* __restrict__ q,
                  const float* __restrict__ f0, const float* __restrict__ f1,
                  const float* __restrict__ f2, const float* __restrict__ f3,
                  __nv_bfloat16* __restrict__ oq, __nv_bfloat16* __restrict__ of)
{
    __shared__ float t[32][33];
    int sel = 0;
    while ((int)blockIdx.x >= c_fts[sel + 1]) sel++;
    const int tile0 = blockIdx.x - c_fts[sel];
    const int b = blockIdx.z;
    int P; const float* I; __nv_bfloat16* O;
    if (sel == 0) {
        P = 4096; I = q + (long)b * 256 * HW; O = oq + (long)b * HW * ABF;
    } else {
        int lvl = sel - 1;
        P = c_mact[lvl];
        I = (lvl == 0 ? f0 : lvl == 1 ? f1 : lvl == 2 ? f2 : f3) + (long)b * 256 * P;
        O = of + (long)b * VPIX * ABF + (long)c_vpix[lvl] * ABF;
    }
    const int p0 = tile0 * 32, c0 = blockIdx.y * 32;
    const int tx = threadIdx.x & 31, ty = threadIdx.x >> 5;
#pragma unroll
    for (int i = 0; i < 32; i += 8)
        t[ty + i][tx] = I[(long)(c0 + ty + i) * P + p0 + tx];
    __syncthreads();
#pragma unroll
    for (int i = 0; i < 32; i += 8) {
        __nv_bfloat16 h, l;
        split_bf(t[tx][ty + i], h, l);
        long e = (long)(p0 + ty + i) * ABF + c0 + tx;
        O[e] = h; O[e + 256] = l;
    }
}

// ---------------------------------------------------------------------------
// All weight prep in one launch.
// ---------------------------------------------------------------------------
#define SEG0 262144              // v_w -> g_vw (B-format)
#define SEG1 (SEG0 + 65536)      // out_w -> g_ow
#define SEG2 (SEG1 + 884736)     // off/attn_w -> g_Woa (A-format)
#define SEG3 (SEG2 + 65536)      // q_w^T -> g_qwT (B-format)
#define SEG4 (SEG3 + 384)        // biases
#define SEG5 (SEG4 + 256)        // bn

__global__ void prep_all(const float* __restrict__ qw, const float* __restrict__ vw,
                         const float* __restrict__ ow,
                         const float* __restrict__ offw, const float* __restrict__ attw,
                         const float* __restrict__ offb, const float* __restrict__ attb,
                         const float* __restrict__ bg, const float* __restrict__ bb,
                         const float* __restrict__ bm, const float* __restrict__ bv)
{
    long i = (long)blockIdx.x * 256 + threadIdx.x;
    if (i < SEG0) {
        long l = i >> 16, rem = i & 65535;
        long o = rem >> 8, c = rem & 255;
        __nv_bfloat16 h, lo;
        split_bf(vw[i], h, lo);
        long e = l * (256 * ABF) + o * ABF + c;
        g_vw[e] = h; g_vw[e + 256] = lo;
    } else if (i < SEG1) {
        long j = i - SEG0;
        long o = j >> 8, c = j & 255;
        __nv_bfloat16 h, lo;
        split_bf(ow[j], h, lo);
        g_ow[o * ABF + c] = h; g_ow[o * ABF + c + 256] = lo;
    } else if (i < SEG2) {
        long j = i - SEG1;
        long row = j >> 8, m = j & 255;
        long tap = row / 384, o = row - tap * 384;
        float v = (o < 256) ? offw[(o * 256 + m) * 9 + tap]
                            : attw[((o - 256) * 256 + m) * 9 + tap];
        __nv_bfloat16 h, lo;
        split_bf(v, h, lo);
        g_Woa[row * ABF + m] = h; g_Woa[row * ABF + m + 256] = lo;
    } else if (i < SEG3) {
        long j = i - SEG2;
        long c = j >> 8, m = j & 255;
        __nv_bfloat16 h, lo;
        split_bf(qw[m * 256 + c], h, lo);
        g_qwT[c * ABF + m] = h; g_qwT[c * ABF + m + 256] = lo;
    } else if (i < SEG4) {
        long j = i - SEG3;
        g_cb[j] = (j < 256) ? offb[j] : attb[j - 256];
    } else if (i < SEG5) {
        long j = i - SEG4;
        float s = bg[j] * rsqrtf(bv[j] + BN_EPS);
        g_bns[j] = s;
        g_bnb[j] = bb[j] - bm[j] * s;
    }
}

// ---------------------------------------------------------------------------
// Deformable sampling. One warp per (b, head, pixel). Split-bf16 output.
// ---------------------------------------------------------------------------
__global__ __launch_bounds__(256)
void sample_kernel()
{
    const int warp = threadIdx.x >> 5;
    const int lane = threadIdx.x & 31;
    const int pix  = blockIdx.x * 8 + warp;
    const int h    = blockIdx.y;
    const int b    = blockIdx.z;

    const int ph = pix >> 6;
    const int pw = pix & 63;
    const float refx = -1.f + 2.f * (float)pw / 63.f;
    const float refy = -1.f + 2.f * (float)ph / 63.f;

    const float* cvp = g_cv + ((long)b * HW + pix) * 384;
    float lg = -INFINITY, ox = 0.f, oy = 0.f;
    if (lane < 16) {
        lg = cvp[256 + h * 16 + lane];
        ox = tanhf(cvp[h * 32 + 2 * lane    ]) * 0.25f;
        oy = tanhf(cvp[h * 32 + 2 * lane + 1]) * 0.25f;
    }
    float mx = lg;
#pragma unroll
    for (int s = 16; s > 0; s >>= 1)
        mx = fmaxf(mx, __shfl_xor_sync(0xFFFFFFFFu, mx, s));
    float e = (lane < 16) ? expf(lg - mx) : 0.f;
    float sum = e;
#pragma unroll
    for (int s = 16; s > 0; s >>= 1)
        sum += __shfl_xor_sync(0xFFFFFFFFu, sum, s);
    float wgt = e / sum;

    const float* vb = g_v + (long)b * VSTRF + h * 32 + lane;

    float acc = 0.f;
#pragma unroll
    for (int i = 0; i < 16; i++) {
        const int lvl = i >> 2;
        const int sz  = 64 >> lvl;
        float aw = __shfl_sync(0xFFFFFFFFu, wgt, i);
        float gx = refx + __shfl_sync(0xFFFFFFFFu, ox, i);
        float gy = refy + __shfl_sync(0xFFFFFFFFu, oy, i);

        float xf = (gx + 1.f) * 0.5f * (float)(sz - 1);
        float yf = (gy + 1.f) * 0.5f * (float)(sz - 1);
        float x0f = floorf(xf), y0f = floorf(yf);
        int x0 = (int)x0f, y0 = (int)y0f;
        int x1 = x0 + 1,  y1 = y0 + 1;
        float wx1 = xf - x0f, wx0 = 1.f - wx1;
        float wy1 = yf - y0f, wy0 = 1.f - wy1;

        const float* vl = vb + c_voff[lvl];
        if (x0 >= 0 && x0 < sz && y0 >= 0 && y0 < sz)
            acc = fmaf(aw * wx0 * wy0, vl[(y0 * sz + x0) * 256], acc);
        if (x1 >= 0 && x1 < sz && y0 >= 0 && y0 < sz)
            acc = fmaf(aw * wx1 * wy0, vl[(y0 * sz + x1) * 256], acc);
        if (x0 >= 0 && x0 < sz && y1 >= 0 && y1 < sz)
            acc = fmaf(aw * wx0 * wy1, vl[(y1 * sz + x0) * 256], acc);
        if (x1 >= 0 && x1 < sz && y1 >= 0 && y1 < sz)
            acc = fmaf(aw * wx1 * wy1, vl[(y1 * sz + x1) * 256], acc);
    }

    __nv_bfloat16 hh, ll;
    split_bf(acc, hh, ll);
    long ebase = ((long)b * HW + pix) * ABF + h * 32 + lane;
    g_att[ebase] = hh; g_att[ebase + 256] = ll;
}

// ---------------------------------------------------------------------------
// Launch. 6 launches; merged conv+vproj GEMM is the 4th (ncu capture slot).
// ---------------------------------------------------------------------------
extern "C" void kernel_launch(void* const* d_in, const int* in_sizes, int n_in,
                              void* d_out, int out_size)
{
    const float* query  = (const float*)d_in[0];
    const float* feat0  = (const float*)d_in[1];
    const float* feat1  = (const float*)d_in[2];
    const float* feat2  = (const float*)d_in[3];
    const float* feat3  = (const float*)d_in[4];
    const float* q_w    = (const float*)d_in[5];
    const float* v_w    = (const float*)d_in[6];
    const float* out_w  = (const float*)d_in[7];
    const float* off_w  = (const float*)d_in[8];
    const float* off_b  = (const float*)d_in[9];
    const float* attn_w = (const float*)d_in[10];
    const float* attn_b = (const float*)d_in[11];
    const float* bn_g   = (const float*)d_in[12];
    const float* bn_b   = (const float*)d_in[13];
    const float* bn_m   = (const float*)d_in[14];
    const float* bn_v   = (const float*)d_in[15];
    float* out = (float*)d_out;

    void* p;
    __nv_bfloat16 *gqT, *gfT;
    cudaGetSymbolAddress(&p, g_qT);  gqT  = (__nv_bfloat16*)p;
    cudaGetSymbolAddress(&p, g_fT);  gfT  = (__nv_bfloat16*)p;

    cudaFuncSetAttribute(mm_all, cudaFuncAttributeMaxDynamicSharedMemorySize, DSMEM_SZ);

    // 1. weight prep
    prep_all<<<(SEG5 + 255) / 256, 256>>>(q_w, v_w, out_w, off_w, attn_w,
                                          off_b, attn_b, bn_g, bn_b, bn_m, bn_v);
    // 2. all transposes (query + 4 levels)
    transposeAll<<<dim3(298, 8, BATCH), 256>>>(query, feat0, feat1, feat2, feat3,
                                               gqT, gfT);
    // 3. compose conv weights
    mm_all<<<dim3(27, 2, 1), 256, DSMEM_SZ>>>(0, nullptr, nullptr);

    // 4. merged conv + vproj GEMM   <-- ncu capture slot
    mm_all<<<dim3(182, 1, BATCH), 256, DSMEM_SZ>>>(1, nullptr, nullptr);

    // 5. deformable sampling
    sample_kernel<<<dim3(512, 8, BATCH), 256>>>();

    // 6. output projection + residual + BN + SiLU
    mm_all<<<dim3(32, 2, BATCH), 256, DSMEM_SZ>>>(3, query, out);
}